// round 3
// baseline (speedup 1.0000x reference)
#include <cuda_runtime.h>
#include <math.h>

#define N_DRUG 11000
#define N_PRO  1000
#define NTOT   12000
#define NE     192000
#define OFF_MU 144000000L
#define OFF_LV 145536000L

// ---------------- static scratch (no allocations allowed) ----------------
__device__ float g_d1[N_DRUG*128];
__device__ float g_d2[N_DRUG*256];
__device__ float g_X[NTOT*128];
__device__ float g_W2d[N_PRO*256];
__device__ float g_Gt[26*256*128];
__device__ float g_M[26L*N_PRO*128];
__device__ float g_pbias[128];
__device__ float g_XW1[NTOT*256];
__device__ float g_H1b[NTOT*256];
__device__ float g_HW[NTOT*256];
__device__ float g_gc23[256*256];
__device__ int   g_cnt[NTOT];
__device__ int   g_rp[NTOT+1];
__device__ int   g_cur[NTOT];
__device__ int   g_ccol[NE];
__device__ float g_cval[NE];

// ---------------- f32x2 helpers ----------------
__device__ __forceinline__ unsigned long long dupf2(float a) {
    unsigned long long r;
    asm("mov.b64 %0, {%1, %1};" : "=l"(r) : "f"(a));
    return r;
}
__device__ __forceinline__ void fma2(unsigned long long& d, unsigned long long a, unsigned long long b) {
    asm("fma.rn.f32x2 %0, %1, %2, %0;" : "+l"(d) : "l"(a), "l"(b));
}

// ---------------- CSR build ----------------
__global__ void zero_cnt_kernel() {
    int i = blockIdx.x * 256 + threadIdx.x;
    if (i < NTOT) g_cnt[i] = 0;
}
__global__ void count_kernel(const int* __restrict__ rows) {
    int e = blockIdx.x * 256 + threadIdx.x;
    if (e < NE) atomicAdd(&g_cnt[rows[e]], 1);
}
__global__ void scan_kernel() {
    __shared__ int sums[1024];
    int tid = threadIdx.x;
    const int CH = (NTOT + 1023) / 1024;   // 12
    int base = tid * CH;
    int s = 0;
    for (int i = 0; i < CH; i++) { int idx = base + i; if (idx < NTOT) s += g_cnt[idx]; }
    sums[tid] = s;
    __syncthreads();
    for (int off = 1; off < 1024; off <<= 1) {
        int v = 0;
        if (tid >= off) v = sums[tid - off];
        __syncthreads();
        sums[tid] += v;
        __syncthreads();
    }
    int prefix = (tid == 0) ? 0 : sums[tid - 1];
    for (int i = 0; i < CH; i++) {
        int idx = base + i;
        if (idx < NTOT) { g_rp[idx] = prefix; g_cur[idx] = prefix; prefix += g_cnt[idx]; }
    }
    if (tid == 1023) g_rp[NTOT] = NE;
}
__global__ void scatter_kernel(const int* __restrict__ rows, const int* __restrict__ cols,
                               const float* __restrict__ vals) {
    int e = blockIdx.x * 256 + threadIdx.x;
    if (e < NE) {
        int r = rows[e];
        int pos = atomicAdd(&g_cur[r], 1);
        g_ccol[pos] = cols[e];
        g_cval[pos] = vals[e];
    }
}

// ---------------- generic tiled GEMM: C[M,N] = A[M,K] @ B[K,N] (+bias,relu) ---
// 128x64 tile, 256 threads, 8x4 microtile, optional batch via blockIdx.z.
__global__ __launch_bounds__(256) void gemm_kernel(
    const float* __restrict__ A, const float* __restrict__ B,
    const float* __restrict__ bias, float* __restrict__ C,
    int M, int N, int K, int relu,
    long sA, long sB, long sC)
{
    A += (long)blockIdx.z * sA;
    B += (long)blockIdx.z * sB;
    C += (long)blockIdx.z * sC;
    __shared__ float As[16][132];
    __shared__ float Bs[16][68];
    int tid = threadIdx.x;
    int tx = tid & 15, ty = tid >> 4;
    int m0 = blockIdx.y * 128, n0 = blockIdx.x * 64;
    float acc[8][4];
#pragma unroll
    for (int i = 0; i < 8; i++)
#pragma unroll
        for (int j = 0; j < 4; j++) acc[i][j] = 0.f;

    int ktiles = (K + 15) >> 4;
    for (int kt = 0; kt < ktiles; kt++) {
        int k0 = kt << 4;
#pragma unroll
        for (int l = 0; l < 8; l++) {
            int idx = tid + l * 256;
            int k = idx & 15, m = idx >> 4;
            int gm = m0 + m, gk = k0 + k;
            As[k][m] = (gm < M && gk < K) ? A[(long)gm * K + gk] : 0.f;
        }
#pragma unroll
        for (int l = 0; l < 4; l++) {
            int idx = tid + l * 256;
            int n = idx & 63, k = idx >> 6;
            int gk = k0 + k, gn = n0 + n;
            Bs[k][n] = (gk < K && gn < N) ? B[(long)gk * N + gn] : 0.f;
        }
        __syncthreads();
#pragma unroll
        for (int k = 0; k < 16; k++) {
            float4 a0 = *(const float4*)&As[k][ty * 8];
            float4 a1 = *(const float4*)&As[k][ty * 8 + 4];
            float4 b  = *(const float4*)&Bs[k][tx * 4];
            float av[8] = {a0.x, a0.y, a0.z, a0.w, a1.x, a1.y, a1.z, a1.w};
            float bv[4] = {b.x, b.y, b.z, b.w};
#pragma unroll
            for (int i = 0; i < 8; i++)
#pragma unroll
                for (int j = 0; j < 4; j++) acc[i][j] += av[i] * bv[j];
        }
        __syncthreads();
    }
#pragma unroll
    for (int i = 0; i < 8; i++) {
        int gm = m0 + ty * 8 + i;
        if (gm >= M) continue;
#pragma unroll
        for (int j = 0; j < 4; j++) {
            int gn = n0 + tx * 4 + j;
            if (gn >= N) continue;
            float v = acc[i][j];
            if (bias) v += bias[gn];
            if (relu) v = fmaxf(v, 0.f);
            C[(long)gm * N + gn] = v;
        }
    }
}

// ---------------- protein branch ----------------
__global__ void repack_w_kernel(const float* __restrict__ conv_w) {
    int idx = blockIdx.x * 256 + threadIdx.x;   // 256000
    if (idx < N_PRO * 256) {
        int i = idx >> 8, ok = idx & 255;
        int o = ok >> 3, k = ok & 7;
        g_W2d[idx] = conv_w[((long)o * N_PRO + i) * 8 + k];
    }
}
// Gt[t][ok][f] = sum_h emb[t, h+k] * fc_w[(o*121+h)*128 + f]
__global__ void g_kernel(const float* __restrict__ emb, const float* __restrict__ fc_w) {
    int idx = blockIdx.x;          // t*256 + ok   (26*256 blocks)
    int t = idx >> 8, ok = idx & 255;
    int o = ok >> 3, kk = ok & 7;
    int f = threadIdx.x;           // 128
    __shared__ float e[128];
    if (f < 121) e[f] = emb[t * 128 + kk + f];
    __syncthreads();
    float acc = 0.f;
#pragma unroll 4
    for (int h = 0; h < 121; h++)
        acc += e[h] * fc_w[(o * 121 + h) * 128 + f];
    g_Gt[(long)idx * 128 + f] = acc;
}
__global__ void pbias_kernel(const float* __restrict__ fc_b, const float* __restrict__ conv_b,
                             const float* __restrict__ fc_w) {
    int f = threadIdx.x;   // 128
    float acc = fc_b[f];
    for (int o = 0; o < 32; o++) {
        float cb = conv_b[o];
        for (int h = 0; h < 121; h++) acc += cb * fc_w[(o * 121 + h) * 128 + f];
    }
    g_pbias[f] = acc;
}
// X[11000+p][f] = pbias[f] + sum_i M[tok(p,i)][i][f]
__global__ void protein_gather_kernel(const int* __restrict__ pro_x) {
    int p = blockIdx.x, f = threadIdx.x;   // 1000 blocks x 128
    __shared__ int tok[128];
    float acc = g_pbias[f];
    for (int c = 0; c < 1000; c += 128) {
        int n = min(128, 1000 - c);
        if (f < n) tok[f] = pro_x[p * 1000 + c + f];
        __syncthreads();
#pragma unroll 8
        for (int ii = 0; ii < n; ii++) {
            int t = tok[ii];
            acc += g_M[((long)t * N_PRO + c + ii) * 128 + f];
        }
        __syncthreads();
    }
    g_X[(long)(N_DRUG + p) * 128 + f] = acc;
}
__global__ void repack_gc23_kernel(const float* __restrict__ gc2, const float* __restrict__ gc3) {
    int idx = blockIdx.x * 256 + threadIdx.x;   // 256*256
    int r = idx >> 8, c = idx & 255;
    g_gc23[idx] = (c < 128) ? gc2[r * 128 + c] : gc3[r * 128 + c - 128];
}

// ---------------- SpMM (CSR gather), F=256, optional split output -----------
__global__ void spmm256_kernel(const float* __restrict__ Xin,
                               float* __restrict__ out1, float* __restrict__ out2, int relu) {
    int r = blockIdx.x;
    int f = threadIdx.x;   // 256
    int e0 = g_rp[r], e1 = g_rp[r + 1];
    float acc = 0.f;
    for (int e = e0; e < e1; e++) {
        int c = g_ccol[e];
        float v = g_cval[e];
        acc += v * Xin[(long)c * 256 + f];
    }
    if (relu) acc = fmaxf(acc, 0.f);
    if (out2) {
        if (f < 128) out1[(long)r * 128 + f] = acc;
        else         out2[(long)r * 128 + f - 128] = acc;
    } else {
        out1[(long)r * 256 + f] = acc;
    }
}

// ---------------- SYRK: C = Z Z^T, Z[12000,128], symmetric, FFMA2 ----------
__global__ __launch_bounds__(256, 2) void syrk_kernel(const float* __restrict__ Z,
                                                      float* __restrict__ C) {
    const int T = 94;
    int p = blockIdx.x;
    int ti = (int)((2.0 * T + 1.0 - sqrt((2.0 * T + 1.0) * (2.0 * T + 1.0) - 8.0 * p)) * 0.5);
    if (ti < 0) ti = 0;
    if (ti > T - 1) ti = T - 1;
    while (ti > 0 && ti * T - ti * (ti - 1) / 2 > p) ti--;
    while ((ti + 1) * T - ((ti + 1) * ti) / 2 <= p) ti++;
    int tj = ti + (p - (ti * T - ti * (ti - 1) / 2));
    long i0 = (long)ti * 128, j0 = (long)tj * 128;

    __shared__ float As[16][132];
    __shared__ float Bs[16][132];
    __shared__ float S[32][129];

    int tid = threadIdx.x;
    int tx = tid & 15, ty = tid >> 4;
    unsigned long long acc[8][4];
#pragma unroll
    for (int i = 0; i < 8; i++)
#pragma unroll
        for (int j = 0; j < 4; j++) acc[i][j] = 0ull;

    int r  = tid >> 1;
    int kh = (tid & 1) * 8;

    for (int k0 = 0; k0 < 128; k0 += 16) {
        {
            long gr = i0 + r;
            float4 v0 = make_float4(0.f, 0.f, 0.f, 0.f), v1 = v0;
            if (gr < NTOT) {
                const float4* src = (const float4*)(Z + gr * 128 + k0 + kh);
                v0 = src[0]; v1 = src[1];
            }
            As[kh + 0][r] = v0.x; As[kh + 1][r] = v0.y; As[kh + 2][r] = v0.z; As[kh + 3][r] = v0.w;
            As[kh + 4][r] = v1.x; As[kh + 5][r] = v1.y; As[kh + 6][r] = v1.z; As[kh + 7][r] = v1.w;
            gr = j0 + r;
            v0 = make_float4(0.f, 0.f, 0.f, 0.f); v1 = v0;
            if (gr < NTOT) {
                const float4* src = (const float4*)(Z + gr * 128 + k0 + kh);
                v0 = src[0]; v1 = src[1];
            }
            Bs[kh + 0][r] = v0.x; Bs[kh + 1][r] = v0.y; Bs[kh + 2][r] = v0.z; Bs[kh + 3][r] = v0.w;
            Bs[kh + 4][r] = v1.x; Bs[kh + 5][r] = v1.y; Bs[kh + 6][r] = v1.z; Bs[kh + 7][r] = v1.w;
        }
        __syncthreads();
#pragma unroll
        for (int k = 0; k < 16; k++) {
            float4 a0 = *(const float4*)&As[k][ty * 8];
            float4 a1 = *(const float4*)&As[k][ty * 8 + 4];
            unsigned long long aa[8];
            aa[0] = dupf2(a0.x); aa[1] = dupf2(a0.y); aa[2] = dupf2(a0.z); aa[3] = dupf2(a0.w);
            aa[4] = dupf2(a1.x); aa[5] = dupf2(a1.y); aa[6] = dupf2(a1.z); aa[7] = dupf2(a1.w);
            const ulonglong2* bp = (const ulonglong2*)&Bs[k][tx * 8];
            ulonglong2 b01 = bp[0], b23 = bp[1];
            unsigned long long bb[4] = {b01.x, b01.y, b23.x, b23.y};
#pragma unroll
            for (int i = 0; i < 8; i++)
#pragma unroll
                for (int j = 0; j < 4; j++) fma2(acc[i][j], aa[i], bb[j]);
        }
        __syncthreads();
    }

    float cf[8][8];
#pragma unroll
    for (int i = 0; i < 8; i++)
#pragma unroll
        for (int j = 0; j < 4; j++)
            asm("mov.b64 {%0, %1}, %2;"
                : "=f"(cf[i][2 * j]), "=f"(cf[i][2 * j + 1]) : "l"(acc[i][j]));

    bool full = (i0 + 128 <= NTOT) && (j0 + 128 <= NTOT);

    if (full) {
#pragma unroll
        for (int i = 0; i < 8; i++) {
            long gm = i0 + ty * 8 + i;
            float4* dst = (float4*)(C + gm * (long)NTOT + j0 + tx * 8);
            dst[0] = make_float4(cf[i][0], cf[i][1], cf[i][2], cf[i][3]);
            dst[1] = make_float4(cf[i][4], cf[i][5], cf[i][6], cf[i][7]);
        }
    } else {
#pragma unroll
        for (int i = 0; i < 8; i++) {
            long gm = i0 + ty * 8 + i;
            if (gm >= NTOT) continue;
#pragma unroll
            for (int j = 0; j < 8; j++) {
                long gn = j0 + tx * 8 + j;
                if (gn >= NTOT) continue;
                C[gm * (long)NTOT + gn] = cf[i][j];
            }
        }
    }

    if (ti != tj) {
        if (full) {
#pragma unroll
            for (int ic = 0; ic < 4; ic++) {
                __syncthreads();
                if ((ty >> 2) == ic) {
                    int iw = (ty & 3) * 8;
#pragma unroll
                    for (int i = 0; i < 8; i++)
#pragma unroll
                        for (int j = 0; j < 8; j++)
                            S[iw + i][tx * 8 + j] = cf[i][j];
                }
                __syncthreads();
                int jj = tid >> 1;
                int off = (tid & 1) * 16;
                float* dst = C + (j0 + jj) * (long)NTOT + i0 + ic * 32 + off;
#pragma unroll
                for (int q = 0; q < 4; q++) {
                    float4 v;
                    v.x = S[off + q * 4 + 0][jj];
                    v.y = S[off + q * 4 + 1][jj];
                    v.z = S[off + q * 4 + 2][jj];
                    v.w = S[off + q * 4 + 3][jj];
                    ((float4*)dst)[q] = v;
                }
            }
        } else {
#pragma unroll
            for (int i = 0; i < 8; i++) {
                long gm = i0 + ty * 8 + i;
                if (gm >= NTOT) continue;
#pragma unroll
                for (int j = 0; j < 8; j++) {
                    long gn = j0 + tx * 8 + j;
                    if (gn >= NTOT) continue;
                    C[gn * (long)NTOT + gm] = cf[i][j];
                }
            }
        }
    }
}

// ---------------- host ----------------
extern "C" void kernel_launch(void* const* d_in, const int* in_sizes, int n_in,
                              void* d_out, int out_size) {
    const float* drug_x = (const float*)d_in[0];
    const int*   pro_x  = (const int*)d_in[1];
    const int*   arows  = (const int*)d_in[2];
    const int*   acols  = (const int*)d_in[3];
    const float* avals  = (const float*)d_in[4];
    const float* w1     = (const float*)d_in[5];
    const float* b1     = (const float*)d_in[6];
    const float* w2     = (const float*)d_in[7];
    const float* b2     = (const float*)d_in[8];
    const float* w3     = (const float*)d_in[9];
    const float* b3     = (const float*)d_in[10];
    const float* emb_xt = (const float*)d_in[11];
    const float* conv_w = (const float*)d_in[12];
    const float* conv_b = (const float*)d_in[13];
    const float* fc_w   = (const float*)d_in[14];
    const float* fc_b   = (const float*)d_in[15];
    const float* gc1_w  = (const float*)d_in[16];
    const float* gc2_w  = (const float*)d_in[17];
    const float* gc3_w  = (const float*)d_in[18];
    float* out = (float*)d_out;

    float *pd1, *pd2, *pX, *pW2d, *pGt, *pM, *pXW1, *pH1, *pHW, *pgc23;
    cudaGetSymbolAddress((void**)&pd1,  g_d1);
    cudaGetSymbolAddress((void**)&pd2,  g_d2);
    cudaGetSymbolAddress((void**)&pX,   g_X);
    cudaGetSymbolAddress((void**)&pW2d, g_W2d);
    cudaGetSymbolAddress((void**)&pGt,  g_Gt);
    cudaGetSymbolAddress((void**)&pM,   g_M);
    cudaGetSymbolAddress((void**)&pXW1, g_XW1);
    cudaGetSymbolAddress((void**)&pH1,  g_H1b);
    cudaGetSymbolAddress((void**)&pHW,  g_HW);
    cudaGetSymbolAddress((void**)&pgc23, g_gc23);

    // CSR build
    zero_cnt_kernel<<<47, 256>>>();
    count_kernel<<<750, 256>>>(arows);
    scan_kernel<<<1, 1024>>>();
    scatter_kernel<<<750, 256>>>(arows, acols, avals);

    // drug MLP
    gemm_kernel<<<dim3(2, 86, 1), 256>>>(drug_x, w1, b1, pd1, N_DRUG, 128, 167, 1, 0, 0, 0);
    gemm_kernel<<<dim3(4, 86, 1), 256>>>(pd1, w2, b2, pd2, N_DRUG, 256, 128, 1, 0, 0, 0);
    gemm_kernel<<<dim3(2, 86, 1), 256>>>(pd2, w3, b3, pX, N_DRUG, 128, 256, 1, 0, 0, 0);

    // protein branch (conv+fc refactored)
    repack_w_kernel<<<1000, 256>>>(conv_w);
    g_kernel<<<26 * 256, 128>>>(emb_xt, fc_w);
    pbias_kernel<<<1, 128>>>(fc_b, conv_b, fc_w);
    gemm_kernel<<<dim3(2, 8, 26), 256>>>(pW2d, pGt, nullptr, pM, N_PRO, 128, 256, 0,
                                         0, 256L * 128, (long)N_PRO * 128);
    protein_gather_kernel<<<1000, 128>>>(pro_x);

    // GCN encoder
    repack_gc23_kernel<<<256, 256>>>(gc2_w, gc3_w);
    gemm_kernel<<<dim3(4, 94, 1), 256>>>(pX, gc1_w, nullptr, pXW1, NTOT, 256, 128, 0, 0, 0, 0);
    spmm256_kernel<<<NTOT, 256>>>(pXW1, pH1, nullptr, 1);
    gemm_kernel<<<dim3(4, 94, 1), 256>>>(pH1, pgc23, nullptr, pHW, NTOT, 256, 256, 0, 0, 0, 0);
    spmm256_kernel<<<NTOT, 256>>>(pHW, out + OFF_MU, out + OFF_LV, 0);

    // decoder: adj_rec = Z Z^T with Z = mu (read directly from d_out)
    syrk_kernel<<<4465, 256>>>(out + OFF_MU, out);
}

// round 5
// speedup vs baseline: 1.2322x; 1.2322x over previous
#include <cuda_runtime.h>
#include <cuda_bf16.h>
#include <math.h>
#include <stdint.h>

#define N_DRUG 11000
#define N_PRO  1000
#define NTOT   12000
#define NE     192000
#define OFF_MU 144000000L
#define OFF_LV 145536000L

// ---------------- static scratch (no allocations allowed) ----------------
__device__ float g_d1[N_DRUG*128];
__device__ float g_d2[N_DRUG*256];
__device__ float g_X[NTOT*128];
__device__ float g_W2d[N_PRO*256];
__device__ float g_Gt[26*256*128];
__device__ float g_M[26L*N_PRO*128];
__device__ float g_pbias[128];
__device__ float g_XW1[NTOT*256];
__device__ float g_H1b[NTOT*256];
__device__ float g_HW[NTOT*256];
__device__ float g_gc23[256*256];
__device__ int   g_cnt[NTOT];
__device__ int   g_rp[NTOT+1];
__device__ int   g_cur[NTOT];
__device__ int   g_ccol[NE];
__device__ float g_cval[NE];
__device__ __nv_bfloat16 g_Zhi[NTOT*128];
__device__ __nv_bfloat16 g_Zlo[NTOT*128];

// ---------------- f32x2 helpers ----------------
__device__ __forceinline__ unsigned long long dupf2(float a) {
    unsigned long long r;
    asm("mov.b64 %0, {%1, %1};" : "=l"(r) : "f"(a));
    return r;
}
__device__ __forceinline__ void fma2(unsigned long long& d, unsigned long long a, unsigned long long b) {
    asm("fma.rn.f32x2 %0, %1, %2, %0;" : "+l"(d) : "l"(a), "l"(b));
}

__device__ __forceinline__ uint32_t smem_to_u32(const void* smem_ptr) {
    uint32_t addr;
    asm("{ .reg .u64 tmp; cvta.to.shared.u64 tmp, %1; cvt.u32.u64 %0, tmp; }"
        : "=r"(addr) : "l"(smem_ptr));
    return addr;
}

// ---------------- warp-level tensor-core primitives (sm_80+ baseline PTX) ----
#define LDSM_X4(r, addr) \
    asm volatile("ldmatrix.sync.aligned.m8n8.x4.shared.b16 {%0,%1,%2,%3}, [%4];" \
        : "=r"((r)[0]), "=r"((r)[1]), "=r"((r)[2]), "=r"((r)[3]) : "r"(addr))
#define LDSM_X2(r, addr) \
    asm volatile("ldmatrix.sync.aligned.m8n8.x2.shared.b16 {%0,%1}, [%2];" \
        : "=r"((r)[0]), "=r"((r)[1]) : "r"(addr))
#define MMA_BF16(c, a, b) \
    asm volatile("mma.sync.aligned.m16n8k16.row.col.f32.bf16.bf16.f32 " \
        "{%0,%1,%2,%3}, {%4,%5,%6,%7}, {%8,%9}, {%0,%1,%2,%3};" \
        : "+f"((c)[0]), "+f"((c)[1]), "+f"((c)[2]), "+f"((c)[3]) \
        : "r"((a)[0]), "r"((a)[1]), "r"((a)[2]), "r"((a)[3]), \
          "r"((b)[0]), "r"((b)[1]))

// ---------------- CSR build ----------------
__global__ void zero_cnt_kernel() {
    int i = blockIdx.x * 256 + threadIdx.x;
    if (i < NTOT) g_cnt[i] = 0;
}
__global__ void count_kernel(const int* __restrict__ rows) {
    int e = blockIdx.x * 256 + threadIdx.x;
    if (e < NE) atomicAdd(&g_cnt[rows[e]], 1);
}
__global__ void scan_kernel() {
    __shared__ int sums[1024];
    int tid = threadIdx.x;
    const int CH = (NTOT + 1023) / 1024;   // 12
    int base = tid * CH;
    int s = 0;
    for (int i = 0; i < CH; i++) { int idx = base + i; if (idx < NTOT) s += g_cnt[idx]; }
    sums[tid] = s;
    __syncthreads();
    for (int off = 1; off < 1024; off <<= 1) {
        int v = 0;
        if (tid >= off) v = sums[tid - off];
        __syncthreads();
        sums[tid] += v;
        __syncthreads();
    }
    int prefix = (tid == 0) ? 0 : sums[tid - 1];
    for (int i = 0; i < CH; i++) {
        int idx = base + i;
        if (idx < NTOT) { g_rp[idx] = prefix; g_cur[idx] = prefix; prefix += g_cnt[idx]; }
    }
    if (tid == 1023) g_rp[NTOT] = NE;
}
__global__ void scatter_kernel(const int* __restrict__ rows, const int* __restrict__ cols,
                               const float* __restrict__ vals) {
    int e = blockIdx.x * 256 + threadIdx.x;
    if (e < NE) {
        int r = rows[e];
        int pos = atomicAdd(&g_cur[r], 1);
        g_ccol[pos] = cols[e];
        g_cval[pos] = vals[e];
    }
}

// ---------------- generic tiled GEMM (FFMA2): C[M,N] = A[M,K] @ B[K,N] -------
__global__ __launch_bounds__(256) void gemm_kernel(
    const float* __restrict__ A, const float* __restrict__ B,
    const float* __restrict__ bias, float* __restrict__ C,
    int M, int N, int K, int relu,
    long sA, long sB, long sC)
{
    A += (long)blockIdx.z * sA;
    B += (long)blockIdx.z * sB;
    C += (long)blockIdx.z * sC;
    __shared__ float As[16][132];
    __shared__ float Bs[16][68];
    int tid = threadIdx.x;
    int tx = tid & 15, ty = tid >> 4;
    int m0 = blockIdx.y * 128, n0 = blockIdx.x * 64;
    unsigned long long acc[4][4];   // row-pair p (rows 2p,2p+1) x col j
#pragma unroll
    for (int i = 0; i < 4; i++)
#pragma unroll
        for (int j = 0; j < 4; j++) acc[i][j] = 0ull;

    int ktiles = (K + 15) >> 4;
    for (int kt = 0; kt < ktiles; kt++) {
        int k0 = kt << 4;
#pragma unroll
        for (int l = 0; l < 8; l++) {
            int idx = tid + l * 256;
            int k = idx & 15, m = idx >> 4;
            int gm = m0 + m, gk = k0 + k;
            As[k][m] = (gm < M && gk < K) ? A[(long)gm * K + gk] : 0.f;
        }
#pragma unroll
        for (int l = 0; l < 4; l++) {
            int idx = tid + l * 256;
            int n = idx & 63, k = idx >> 6;
            int gk = k0 + k, gn = n0 + n;
            Bs[k][n] = (gk < K && gn < N) ? B[(long)gk * N + gn] : 0.f;
        }
        __syncthreads();
#pragma unroll
        for (int k = 0; k < 16; k++) {
            ulonglong2 aA = *(const ulonglong2*)&As[k][ty * 8];
            ulonglong2 aB = *(const ulonglong2*)&As[k][ty * 8 + 4];
            float4 b  = *(const float4*)&Bs[k][tx * 4];
            unsigned long long ap[4] = {aA.x, aA.y, aB.x, aB.y};
            unsigned long long bb[4] = {dupf2(b.x), dupf2(b.y), dupf2(b.z), dupf2(b.w)};
#pragma unroll
            for (int p = 0; p < 4; p++)
#pragma unroll
                for (int j = 0; j < 4; j++) fma2(acc[p][j], ap[p], bb[j]);
        }
        __syncthreads();
    }
    float cf[8][4];
#pragma unroll
    for (int p = 0; p < 4; p++)
#pragma unroll
        for (int j = 0; j < 4; j++)
            asm("mov.b64 {%0, %1}, %2;"
                : "=f"(cf[2 * p][j]), "=f"(cf[2 * p + 1][j]) : "l"(acc[p][j]));
#pragma unroll
    for (int i = 0; i < 8; i++) {
        int gm = m0 + ty * 8 + i;
        if (gm >= M) continue;
#pragma unroll
        for (int j = 0; j < 4; j++) {
            int gn = n0 + tx * 4 + j;
            if (gn >= N) continue;
            float v = cf[i][j];
            if (bias) v += bias[gn];
            if (relu) v = fmaxf(v, 0.f);
            C[(long)gm * N + gn] = v;
        }
    }
}

// ---------------- protein branch ----------------
__global__ void repack_w_kernel(const float* __restrict__ conv_w) {
    int idx = blockIdx.x * 256 + threadIdx.x;   // 256000
    if (idx < N_PRO * 256) {
        int i = idx >> 8, ok = idx & 255;
        int o = ok >> 3, k = ok & 7;
        g_W2d[idx] = conv_w[((long)o * N_PRO + i) * 8 + k];
    }
}
__global__ void g_kernel(const float* __restrict__ emb, const float* __restrict__ fc_w) {
    int idx = blockIdx.x;          // t*256 + ok   (26*256 blocks)
    int t = idx >> 8, ok = idx & 255;
    int o = ok >> 3, kk = ok & 7;
    int f = threadIdx.x;           // 128
    __shared__ float e[128];
    if (f < 121) e[f] = emb[t * 128 + kk + f];
    __syncthreads();
    float acc = 0.f;
#pragma unroll 4
    for (int h = 0; h < 121; h++)
        acc += e[h] * fc_w[(o * 121 + h) * 128 + f];
    g_Gt[(long)idx * 128 + f] = acc;
}
__global__ void pbias_kernel(const float* __restrict__ fc_b, const float* __restrict__ conv_b,
                             const float* __restrict__ fc_w) {
    int f = threadIdx.x;   // 128
    float acc = fc_b[f];
    for (int o = 0; o < 32; o++) {
        float cb = conv_b[o];
        for (int h = 0; h < 121; h++) acc += cb * fc_w[(o * 121 + h) * 128 + f];
    }
    g_pbias[f] = acc;
}
__global__ void protein_gather_kernel(const int* __restrict__ pro_x) {
    int p = blockIdx.x, f = threadIdx.x;   // 1000 blocks x 128
    __shared__ int tok[128];
    float acc = g_pbias[f];
    for (int c = 0; c < 1000; c += 128) {
        int n = min(128, 1000 - c);
        if (f < n) tok[f] = pro_x[p * 1000 + c + f];
        __syncthreads();
#pragma unroll 8
        for (int ii = 0; ii < n; ii++) {
            int t = tok[ii];
            acc += g_M[((long)t * N_PRO + c + ii) * 128 + f];
        }
        __syncthreads();
    }
    g_X[(long)(N_DRUG + p) * 128 + f] = acc;
}
__global__ void repack_gc23_kernel(const float* __restrict__ gc2, const float* __restrict__ gc3) {
    int idx = blockIdx.x * 256 + threadIdx.x;   // 256*256
    int r = idx >> 8, c = idx & 255;
    g_gc23[idx] = (c < 128) ? gc2[r * 128 + c] : gc3[r * 128 + c - 128];
}

// ---------------- SpMM (CSR gather), F=256, optional split output -----------
__global__ void spmm256_kernel(const float* __restrict__ Xin,
                               float* __restrict__ out1, float* __restrict__ out2, int relu) {
    int r = blockIdx.x;
    int f = threadIdx.x;   // 256
    int e0 = g_rp[r], e1 = g_rp[r + 1];
    float acc = 0.f;
    for (int e = e0; e < e1; e++) {
        int c = g_ccol[e];
        float v = g_cval[e];
        acc += v * Xin[(long)c * 256 + f];
    }
    if (relu) acc = fmaxf(acc, 0.f);
    if (out2) {
        if (f < 128) out1[(long)r * 128 + f] = acc;
        else         out2[(long)r * 128 + f - 128] = acc;
    } else {
        out1[(long)r * 256 + f] = acc;
    }
}

// ---------------- split Z into bf16 hi/lo ----------------
__global__ void split_kernel(const float* __restrict__ z) {
    int i = blockIdx.x * 256 + threadIdx.x;
    if (i < NTOT * 128) {
        float v = z[i];
        __nv_bfloat16 h = __float2bfloat16(v);
        g_Zhi[i] = h;
        g_Zlo[i] = __float2bfloat16(v - __bfloat162float(h));
    }
}

// ---------------- SYRK via mma.sync bf16 hi/lo: C = Z Z^T --------------------
// SMEM tiles: 128 rows x 136 bf16 (272B pitch, conflict-free for ldmatrix).
// Warp w computes 64x32 region: m offset (w&1)*64, n offset (w>>1)*32.
#define SY_PITCH_B 272
#define SY_TILE_BYTES (128 * SY_PITCH_B)          // 34816
#define SY_SMEM_TOTAL (4 * SY_TILE_BYTES)         // 139264

__device__ __forceinline__ void ld_tile(char* smem, int off,
                                        const __nv_bfloat16* __restrict__ src,
                                        long row0, int r, int half) {
    long gr = row0 + r;
    uint4 v[8];
    if (gr < NTOT) {
        const uint4* s = reinterpret_cast<const uint4*>(src + gr * 128 + half * 64);
#pragma unroll
        for (int c = 0; c < 8; c++) v[c] = s[c];
    } else {
#pragma unroll
        for (int c = 0; c < 8; c++) v[c] = make_uint4(0, 0, 0, 0);
    }
    uint4* d = reinterpret_cast<uint4*>(smem + off + r * SY_PITCH_B + half * 128);
#pragma unroll
    for (int c = 0; c < 8; c++) d[c] = v[c];
}

__global__ __launch_bounds__(256, 1) void syrk_mma_kernel(float* __restrict__ C) {
    extern __shared__ char smem[];
    const int T = 94;
    int p = blockIdx.x;
    int ti = (int)((2.0 * T + 1.0 - sqrt((2.0 * T + 1.0) * (2.0 * T + 1.0) - 8.0 * p)) * 0.5);
    if (ti < 0) ti = 0;
    if (ti > T - 1) ti = T - 1;
    while (ti > 0 && ti * T - ti * (ti - 1) / 2 > p) ti--;
    while ((ti + 1) * T - ((ti + 1) * ti) / 2 <= p) ti++;
    int tj = ti + (p - (ti * T - ti * (ti - 1) / 2));
    long i0 = (long)ti * 128, j0 = (long)tj * 128;
    bool offdiag = (ti != tj);

    int tid = threadIdx.x, lane = tid & 31, wid = tid >> 5;

    // cooperative tile loads: thread -> (row, 128B half)
    {
        int r = tid >> 1, half = tid & 1;
        ld_tile(smem, 0,                 g_Zhi, i0, r, half);
        ld_tile(smem, SY_TILE_BYTES,     g_Zlo, i0, r, half);
        if (offdiag) {
            ld_tile(smem, 2 * SY_TILE_BYTES, g_Zhi, j0, r, half);
            ld_tile(smem, 3 * SY_TILE_BYTES, g_Zlo, j0, r, half);
        }
    }
    __syncthreads();

    uint32_t sb = smem_to_u32(smem);
    uint32_t offA_hi = 0, offA_lo = SY_TILE_BYTES;
    uint32_t offB_hi = offdiag ? 2u * SY_TILE_BYTES : 0u;
    uint32_t offB_lo = offdiag ? 3u * SY_TILE_BYTES : (uint32_t)SY_TILE_BYTES;

    int mw = (wid & 1) << 6;   // 0 or 64
    int nw = (wid >> 1) << 5;  // 0,32,64,96

    float acc[4][4][4];
#pragma unroll
    for (int a = 0; a < 4; a++)
#pragma unroll
        for (int b = 0; b < 4; b++)
#pragma unroll
            for (int c = 0; c < 4; c++) acc[a][b][c] = 0.f;

    // ldmatrix lane addressing components
    int arow = mw + (lane & 15);
    uint32_t acol = ((uint32_t)(lane >> 4)) * 16u;       // k-half byte offset
    int brow = nw + (lane & 7);
    uint32_t bcol = ((uint32_t)((lane >> 3) & 1)) * 16u;

#pragma unroll
    for (int ks = 0; ks < 8; ks++) {
        uint32_t kb = (uint32_t)ks * 32u;   // 16 bf16 = 32 bytes per k-step
        uint32_t bh[4][2], bl[4][2];
#pragma unroll
        for (int nf = 0; nf < 4; nf++) {
            uint32_t ro = (uint32_t)(brow + nf * 8) * SY_PITCH_B + kb + bcol;
            LDSM_X2(bh[nf], sb + offB_hi + ro);
            LDSM_X2(bl[nf], sb + offB_lo + ro);
        }
#pragma unroll
        for (int mf = 0; mf < 4; mf++) {
            uint32_t ro = (uint32_t)(arow + mf * 16) * SY_PITCH_B + kb + acol;
            uint32_t ah[4], al[4];
            LDSM_X4(ah, sb + offA_hi + ro);
            LDSM_X4(al, sb + offA_lo + ro);
#pragma unroll
            for (int nf = 0; nf < 4; nf++) {
                MMA_BF16(acc[mf][nf], ah, bh[nf]);
                MMA_BF16(acc[mf][nf], ah, bl[nf]);
                MMA_BF16(acc[mf][nf], al, bh[nf]);
            }
        }
    }
    __syncthreads();   // smem tiles no longer needed

    // D1 = Zi Zj^T direct coalesced store (float2 per fragment row)
    int mrow = lane >> 2, ncol = (lane & 3) * 2;
#pragma unroll
    for (int mf = 0; mf < 4; mf++) {
#pragma unroll
        for (int nf = 0; nf < 4; nf++) {
            long gm = i0 + mw + mf * 16 + mrow;
            long gn = j0 + nw + nf * 8 + ncol;
            if (gn < NTOT) {
                if (gm < NTOT)
                    *(float2*)&C[gm * (long)NTOT + gn] =
                        make_float2(acc[mf][nf][0], acc[mf][nf][1]);
                if (gm + 8 < NTOT)
                    *(float2*)&C[(gm + 8) * (long)NTOT + gn] =
                        make_float2(acc[mf][nf][2], acc[mf][nf][3]);
            }
        }
    }

    // mirror D2 = D1^T via SMEM staging (reuses tile memory), coalesced store
    if (offdiag) {
        float* S = (float*)smem;   // [128][132]
#pragma unroll
        for (int mf = 0; mf < 4; mf++) {
#pragma unroll
            for (int nf = 0; nf < 4; nf++) {
                int ml = mw + mf * 16 + mrow;
                int nl = nw + nf * 8 + ncol;
                S[nl * 132 + ml]           = acc[mf][nf][0];
                S[(nl + 1) * 132 + ml]     = acc[mf][nf][1];
                S[nl * 132 + ml + 8]       = acc[mf][nf][2];
                S[(nl + 1) * 132 + ml + 8] = acc[mf][nf][3];
            }
        }
        __syncthreads();
        int rrow = tid >> 1, half = tid & 1;
        long gn = j0 + rrow;
        if (gn < NTOT) {
            const float* src = &S[rrow * 132 + half * 64];
            float* dst = &C[gn * (long)NTOT + i0 + half * 64];
#pragma unroll
            for (int q = 0; q < 16; q++) {
                long gm = i0 + half * 64 + q * 4;
                if (gm < NTOT) *(float4*)&dst[q * 4] = *(const float4*)&src[q * 4];
            }
        }
    }
}

// ---------------- host ----------------
extern "C" void kernel_launch(void* const* d_in, const int* in_sizes, int n_in,
                              void* d_out, int out_size) {
    const float* drug_x = (const float*)d_in[0];
    const int*   pro_x  = (const int*)d_in[1];
    const int*   arows  = (const int*)d_in[2];
    const int*   acols  = (const int*)d_in[3];
    const float* avals  = (const float*)d_in[4];
    const float* w1     = (const float*)d_in[5];
    const float* b1     = (const float*)d_in[6];
    const float* w2     = (const float*)d_in[7];
    const float* b2     = (const float*)d_in[8];
    const float* w3     = (const float*)d_in[9];
    const float* b3     = (const float*)d_in[10];
    const float* emb_xt = (const float*)d_in[11];
    const float* conv_w = (const float*)d_in[12];
    const float* conv_b = (const float*)d_in[13];
    const float* fc_w   = (const float*)d_in[14];
    const float* fc_b   = (const float*)d_in[15];
    const float* gc1_w  = (const float*)d_in[16];
    const float* gc2_w  = (const float*)d_in[17];
    const float* gc3_w  = (const float*)d_in[18];
    float* out = (float*)d_out;

    float *pd1, *pd2, *pX, *pW2d, *pGt, *pM, *pXW1, *pH1, *pHW, *pgc23;
    cudaGetSymbolAddress((void**)&pd1,  g_d1);
    cudaGetSymbolAddress((void**)&pd2,  g_d2);
    cudaGetSymbolAddress((void**)&pX,   g_X);
    cudaGetSymbolAddress((void**)&pW2d, g_W2d);
    cudaGetSymbolAddress((void**)&pGt,  g_Gt);
    cudaGetSymbolAddress((void**)&pM,   g_M);
    cudaGetSymbolAddress((void**)&pXW1, g_XW1);
    cudaGetSymbolAddress((void**)&pH1,  g_H1b);
    cudaGetSymbolAddress((void**)&pHW,  g_HW);
    cudaGetSymbolAddress((void**)&pgc23, g_gc23);

    static int smem_set = 0;
    if (!smem_set) {
        cudaFuncSetAttribute(syrk_mma_kernel, cudaFuncAttributeMaxDynamicSharedMemorySize,
                             SY_SMEM_TOTAL);
        smem_set = 1;
    }

    // CSR build
    zero_cnt_kernel<<<47, 256>>>();
    count_kernel<<<750, 256>>>(arows);
    scan_kernel<<<1, 1024>>>();
    scatter_kernel<<<750, 256>>>(arows, acols, avals);

    // drug MLP
    gemm_kernel<<<dim3(2, 86, 1), 256>>>(drug_x, w1, b1, pd1, N_DRUG, 128, 167, 1, 0, 0, 0);
    gemm_kernel<<<dim3(4, 86, 1), 256>>>(pd1, w2, b2, pd2, N_DRUG, 256, 128, 1, 0, 0, 0);
    gemm_kernel<<<dim3(2, 86, 1), 256>>>(pd2, w3, b3, pX, N_DRUG, 128, 256, 1, 0, 0, 0);

    // protein branch (conv+fc refactored)
    repack_w_kernel<<<1000, 256>>>(conv_w);
    g_kernel<<<26 * 256, 128>>>(emb_xt, fc_w);
    pbias_kernel<<<1, 128>>>(fc_b, conv_b, fc_w);
    gemm_kernel<<<dim3(2, 8, 26), 256>>>(pW2d, pGt, nullptr, pM, N_PRO, 128, 256, 0,
                                         0, 256L * 128, (long)N_PRO * 128);
    protein_gather_kernel<<<1000, 128>>>(pro_x);

    // GCN encoder
    repack_gc23_kernel<<<256, 256>>>(gc2_w, gc3_w);
    gemm_kernel<<<dim3(4, 94, 1), 256>>>(pX, gc1_w, nullptr, pXW1, NTOT, 256, 128, 0, 0, 0, 0);
    spmm256_kernel<<<NTOT, 256>>>(pXW1, pH1, nullptr, 1);
    gemm_kernel<<<dim3(4, 94, 1), 256>>>(pH1, pgc23, nullptr, pHW, NTOT, 256, 256, 0, 0, 0, 0);
    spmm256_kernel<<<NTOT, 256>>>(pHW, out + OFF_MU, out + OFF_LV, 0);

    // decoder: adj_rec = Z Z^T with Z = mu (mma.sync bf16 hi/lo split)
    split_kernel<<<(NTOT * 128 + 255) / 256, 256>>>(out + OFF_MU);
    syrk_mma_kernel<<<4465, 256, SY_SMEM_TOTAL>>>(out);
}

// round 6
// speedup vs baseline: 1.2735x; 1.0335x over previous
#include <cuda_runtime.h>
#include <cuda_bf16.h>
#include <math.h>
#include <stdint.h>

#define N_DRUG 11000
#define N_PRO  1000
#define NTOT   12000
#define NE     192000
#define OFF_MU 144000000L
#define OFF_LV 145536000L

// ---------------- static scratch (no allocations allowed) ----------------
__device__ float g_M[26L*N_PRO*128];
__device__ float g_pbias[128];
__device__ float g_XW1[NTOT*256];
__device__ float g_HW[NTOT*256];
__device__ int   g_cnt[NTOT];
__device__ int   g_rp[NTOT+1];
__device__ int   g_cur[NTOT];
__device__ int   g_ccol[NE];
__device__ float g_cval[NE];
__device__ __nv_bfloat16 g_Zhi[NTOT*128];
__device__ __nv_bfloat16 g_Zlo[NTOT*128];
// bf16 hi/lo activations
__device__ __nv_bfloat16 g_dxhi[N_DRUG*176], g_dxlo[N_DRUG*176];
__device__ __nv_bfloat16 g_d1hi[N_DRUG*128], g_d1lo[N_DRUG*128];
__device__ __nv_bfloat16 g_d2hi[N_DRUG*256], g_d2lo[N_DRUG*256];
__device__ __nv_bfloat16 g_Xhi[NTOT*128],    g_Xlo[NTOT*128];
__device__ __nv_bfloat16 g_H1hi[NTOT*256],   g_H1lo[NTOT*256];
// bf16 hi/lo transposed weights
__device__ __nv_bfloat16 g_w1thi[128*176],  g_w1tlo[128*176];
__device__ __nv_bfloat16 g_w2thi[256*128],  g_w2tlo[256*128];
__device__ __nv_bfloat16 g_w3thi[128*256],  g_w3tlo[128*256];
__device__ __nv_bfloat16 g_gc1thi[256*128], g_gc1tlo[256*128];
__device__ __nv_bfloat16 g_gc23thi[256*256],g_gc23tlo[256*256];
__device__ __nv_bfloat16 g_W2dhi[N_PRO*256],g_W2dlo[N_PRO*256];
__device__ __nv_bfloat16 g_Gtthi[26L*128*256], g_Gttlo[26L*128*256];

__device__ __forceinline__ uint32_t smem_to_u32(const void* smem_ptr) {
    uint32_t addr;
    asm("{ .reg .u64 tmp; cvta.to.shared.u64 tmp, %1; cvt.u32.u64 %0, tmp; }"
        : "=r"(addr) : "l"(smem_ptr));
    return addr;
}

// ---------------- warp-level tensor-core primitives (sm_80+ baseline PTX) ----
#define LDSM_X4(r, addr) \
    asm volatile("ldmatrix.sync.aligned.m8n8.x4.shared.b16 {%0,%1,%2,%3}, [%4];" \
        : "=r"((r)[0]), "=r"((r)[1]), "=r"((r)[2]), "=r"((r)[3]) : "r"(addr))
#define LDSM_X2(r, addr) \
    asm volatile("ldmatrix.sync.aligned.m8n8.x2.shared.b16 {%0,%1}, [%2];" \
        : "=r"((r)[0]), "=r"((r)[1]) : "r"(addr))
#define MMA_BF16(c, a, b) \
    asm volatile("mma.sync.aligned.m16n8k16.row.col.f32.bf16.bf16.f32 " \
        "{%0,%1,%2,%3}, {%4,%5,%6,%7}, {%8,%9}, {%0,%1,%2,%3};" \
        : "+f"((c)[0]), "+f"((c)[1]), "+f"((c)[2]), "+f"((c)[3]) \
        : "r"((a)[0]), "r"((a)[1]), "r"((a)[2]), "r"((a)[3]), \
          "r"((b)[0]), "r"((b)[1]))

#define SY_PITCH_B 272
#define SY_TILE_BYTES (128 * SY_PITCH_B)          // 34816
#define SY_SMEM_TOTAL (4 * SY_TILE_BYTES)         // 139264

__device__ __forceinline__ void bf16split(float v, __nv_bfloat16& h, __nv_bfloat16& l) {
    h = __float2bfloat16(v);
    l = __float2bfloat16(v - __bfloat162float(h));
}

// ---------------- CSR build ----------------
__global__ void zero_cnt_kernel() {
    int i = blockIdx.x * 256 + threadIdx.x;
    if (i < NTOT) g_cnt[i] = 0;
}
__global__ void count_kernel(const int* __restrict__ rows) {
    int e = blockIdx.x * 256 + threadIdx.x;
    if (e < NE) atomicAdd(&g_cnt[rows[e]], 1);
}
__global__ void scan_kernel() {
    __shared__ int sums[1024];
    int tid = threadIdx.x;
    const int CH = (NTOT + 1023) / 1024;   // 12
    int base = tid * CH;
    int s = 0;
    for (int i = 0; i < CH; i++) { int idx = base + i; if (idx < NTOT) s += g_cnt[idx]; }
    sums[tid] = s;
    __syncthreads();
    for (int off = 1; off < 1024; off <<= 1) {
        int v = 0;
        if (tid >= off) v = sums[tid - off];
        __syncthreads();
        sums[tid] += v;
        __syncthreads();
    }
    int prefix = (tid == 0) ? 0 : sums[tid - 1];
    for (int i = 0; i < CH; i++) {
        int idx = base + i;
        if (idx < NTOT) { g_rp[idx] = prefix; g_cur[idx] = prefix; prefix += g_cnt[idx]; }
    }
    if (tid == 1023) g_rp[NTOT] = NE;
}
__global__ void scatter_kernel(const int* __restrict__ rows, const int* __restrict__ cols,
                               const float* __restrict__ vals) {
    int e = blockIdx.x * 256 + threadIdx.x;
    if (e < NE) {
        int r = rows[e];
        int pos = atomicAdd(&g_cur[r], 1);
        g_ccol[pos] = cols[e];
        g_cval[pos] = vals[e];
    }
}

// ---------------- splits / repacks ----------------
__global__ void dxsplit_kernel(const float* __restrict__ dx) {
    int idx = blockIdx.x * 256 + threadIdx.x;
    if (idx < N_DRUG * 176) {
        int row = idx / 176, col = idx - row * 176;
        float v = (col < 167) ? dx[(long)row * 167 + col] : 0.f;
        bf16split(v, g_dxhi[idx], g_dxlo[idx]);
    }
}
// T[n*ldt + k] = W[k*N + n] (zero-pad k >= K)
__global__ void tsplit_kernel(const float* __restrict__ W, int K, int N, int ldt,
                              __nv_bfloat16* __restrict__ Thi, __nv_bfloat16* __restrict__ Tlo) {
    int idx = blockIdx.x * 256 + threadIdx.x;
    if (idx < N * ldt) {
        int n = idx / ldt, k = idx - n * ldt;
        float v = (k < K) ? W[(long)k * N + n] : 0.f;
        bf16split(v, Thi[idx], Tlo[idx]);
    }
}
__global__ void tsplit23_kernel(const float* __restrict__ gc2, const float* __restrict__ gc3) {
    int idx = blockIdx.x * 256 + threadIdx.x;   // n*256 + k, 65536 total
    int n = idx >> 8, k = idx & 255;
    float v = (n < 128) ? gc2[k * 128 + n] : gc3[k * 128 + n - 128];
    bf16split(v, g_gc23thi[idx], g_gc23tlo[idx]);
}
__global__ void repack_w_kernel(const float* __restrict__ conv_w) {
    int idx = blockIdx.x * 256 + threadIdx.x;   // 256000
    if (idx < N_PRO * 256) {
        int i = idx >> 8, ok = idx & 255;
        int o = ok >> 3, k = ok & 7;
        float v = conv_w[((long)o * N_PRO + i) * 8 + k];
        bf16split(v, g_W2dhi[idx], g_W2dlo[idx]);
    }
}
// Gtt[t][f][ok] = sum_h emb[t, h+k] * fc_w[(o*121+h)*128 + f]   (transposed, split)
__global__ void g_kernel(const float* __restrict__ emb, const float* __restrict__ fc_w) {
    int idx = blockIdx.x;          // t*256 + ok   (26*256 blocks)
    int t = idx >> 8, ok = idx & 255;
    int o = ok >> 3, kk = ok & 7;
    int f = threadIdx.x;           // 128
    __shared__ float e[128];
    if (f < 121) e[f] = emb[t * 128 + kk + f];
    __syncthreads();
    float acc = 0.f;
#pragma unroll 4
    for (int h = 0; h < 121; h++)
        acc += e[h] * fc_w[(o * 121 + h) * 128 + f];
    long dst = ((long)t * 128 + f) * 256 + ok;
    bf16split(acc, g_Gtthi[dst], g_Gttlo[dst]);
}
__global__ void pbias_kernel(const float* __restrict__ fc_b, const float* __restrict__ conv_b,
                             const float* __restrict__ fc_w) {
    int f = threadIdx.x;   // 128
    float acc = fc_b[f];
    for (int o = 0; o < 32; o++) {
        float cb = conv_b[o];
        for (int h = 0; h < 121; h++) acc += cb * fc_w[(o * 121 + h) * 128 + f];
    }
    g_pbias[f] = acc;
}
__global__ void protein_gather_kernel(const int* __restrict__ pro_x) {
    int p = blockIdx.x, f = threadIdx.x;   // 1000 blocks x 128
    __shared__ int tok[128];
    float acc = g_pbias[f];
    for (int c = 0; c < 1000; c += 128) {
        int n = min(128, 1000 - c);
        if (f < n) tok[f] = pro_x[p * 1000 + c + f];
        __syncthreads();
#pragma unroll 8
        for (int ii = 0; ii < n; ii++) {
            int t = tok[ii];
            acc += g_M[((long)t * N_PRO + c + ii) * 128 + f];
        }
        __syncthreads();
    }
    long dst = (long)(N_DRUG + p) * 128 + f;
    bf16split(acc, g_Xhi[dst], g_Xlo[dst]);
}

// ---------------- SpMM (CSR gather), F=256 ----------------------------------
__global__ void spmm256_kernel(const float* __restrict__ Xin,
                               float* __restrict__ out1, float* __restrict__ out2,
                               __nv_bfloat16* __restrict__ bh, __nv_bfloat16* __restrict__ bl,
                               int relu, int split128) {
    int r = blockIdx.x;
    int f = threadIdx.x;   // 256
    int e0 = g_rp[r], e1 = g_rp[r + 1];
    float acc = 0.f;
    for (int e = e0; e < e1; e++) {
        int c = g_ccol[e];
        float v = g_cval[e];
        acc += v * Xin[(long)c * 256 + f];
    }
    if (relu) acc = fmaxf(acc, 0.f);
    if (split128) {
        if (f < 128) {
            out1[(long)r * 128 + f] = acc;
            bf16split(acc, bh[(long)r * 128 + f], bl[(long)r * 128 + f]);
        } else {
            out2[(long)r * 128 + f - 128] = acc;
        }
    } else {
        bf16split(acc, bh[(long)r * 256 + f], bl[(long)r * 256 + f]);
    }
}

// ---------------- tensor-core GEMM: C[M,N] = A[M,K] @ Bt[N,K]^T --------------
// A, Bt given as bf16 hi/lo pairs (k-contiguous rows). 128x128 C tile, 8 warps.
__global__ __launch_bounds__(256, 1) void gemm_mma_kernel(
    const __nv_bfloat16* __restrict__ Ahi, const __nv_bfloat16* __restrict__ Alo, int lda,
    const __nv_bfloat16* __restrict__ Bhi, const __nv_bfloat16* __restrict__ Blo, int ldb,
    const float* __restrict__ bias,
    float* __restrict__ Cf, __nv_bfloat16* __restrict__ Chi, __nv_bfloat16* __restrict__ Clo,
    int ldc, int M, int N, int K, int relu, long sB, long sC)
{
    Bhi += (long)blockIdx.z * sB;
    Blo += (long)blockIdx.z * sB;
    long coff = (long)blockIdx.z * sC;
    extern __shared__ char smem[];
    uint32_t sb = smem_to_u32(smem);

    int tid = threadIdx.x, lane = tid & 31, wid = tid >> 5;
    int m0 = blockIdx.y * 128, n0 = blockIdx.x * 128;

    int mw = (wid & 1) << 6;
    int nw = (wid >> 1) << 5;
    float acc[4][4][4];
#pragma unroll
    for (int a = 0; a < 4; a++)
#pragma unroll
        for (int b = 0; b < 4; b++)
#pragma unroll
            for (int c = 0; c < 4; c++) acc[a][b][c] = 0.f;

    int arow = mw + (lane & 15);
    uint32_t acol = ((uint32_t)(lane >> 4)) * 16u;
    int brow = nw + (lane & 7);
    uint32_t bcol = ((uint32_t)((lane >> 3) & 1)) * 16u;

    int r = tid >> 1, half = tid & 1;

    for (int k0 = 0; k0 < K; k0 += 128) {
        // load 4 tiles (A hi/lo rows m0+r, B hi/lo rows n0+r)
        {
            const __nv_bfloat16* srcs[4] = {Ahi, Alo, Bhi, Blo};
            int lds[4]   = {lda, lda, ldb, ldb};
            int base[4]  = {m0, m0, n0, n0};
            int limit[4] = {M, M, N, N};
#pragma unroll
            for (int tI = 0; tI < 4; tI++) {
                long gr = (long)base[tI] + r;
                bool rv = gr < limit[tI];
                const __nv_bfloat16* sp = srcs[tI] + gr * (long)lds[tI] + k0 + half * 64;
                uint4* d = (uint4*)(smem + tI * SY_TILE_BYTES + r * SY_PITCH_B + half * 128);
#pragma unroll
                for (int c = 0; c < 8; c++) {
                    int col0 = half * 64 + c * 8;
                    uint4 v = make_uint4(0, 0, 0, 0);
                    if (rv && (k0 + col0 + 8) <= K) v = *(const uint4*)(sp + c * 8);
                    d[c] = v;
                }
            }
        }
        __syncthreads();

        int ksteps = (K - k0) >= 128 ? 8 : ((K - k0 + 15) >> 4);
        uint32_t offA_hi = 0, offA_lo = SY_TILE_BYTES;
        uint32_t offB_hi = 2u * SY_TILE_BYTES, offB_lo = 3u * SY_TILE_BYTES;
        if (ksteps == 8) {
#pragma unroll
            for (int ks = 0; ks < 8; ks++) {
                uint32_t kb = (uint32_t)ks * 32u;
                uint32_t bh[4][2], bl[4][2];
#pragma unroll
                for (int nf = 0; nf < 4; nf++) {
                    uint32_t ro = (uint32_t)(brow + nf * 8) * SY_PITCH_B + kb + bcol;
                    LDSM_X2(bh[nf], sb + offB_hi + ro);
                    LDSM_X2(bl[nf], sb + offB_lo + ro);
                }
#pragma unroll
                for (int mf = 0; mf < 4; mf++) {
                    uint32_t ro = (uint32_t)(arow + mf * 16) * SY_PITCH_B + kb + acol;
                    uint32_t ah[4], al[4];
                    LDSM_X4(ah, sb + offA_hi + ro);
                    LDSM_X4(al, sb + offA_lo + ro);
#pragma unroll
                    for (int nf = 0; nf < 4; nf++) {
                        MMA_BF16(acc[mf][nf], ah, bh[nf]);
                        MMA_BF16(acc[mf][nf], ah, bl[nf]);
                        MMA_BF16(acc[mf][nf], al, bh[nf]);
                    }
                }
            }
        } else {
            for (int ks = 0; ks < ksteps; ks++) {
                uint32_t kb = (uint32_t)ks * 32u;
                uint32_t bh[4][2], bl[4][2];
#pragma unroll
                for (int nf = 0; nf < 4; nf++) {
                    uint32_t ro = (uint32_t)(brow + nf * 8) * SY_PITCH_B + kb + bcol;
                    LDSM_X2(bh[nf], sb + offB_hi + ro);
                    LDSM_X2(bl[nf], sb + offB_lo + ro);
                }
#pragma unroll
                for (int mf = 0; mf < 4; mf++) {
                    uint32_t ro = (uint32_t)(arow + mf * 16) * SY_PITCH_B + kb + acol;
                    uint32_t ah[4], al[4];
                    LDSM_X4(ah, sb + offA_hi + ro);
                    LDSM_X4(al, sb + offA_lo + ro);
#pragma unroll
                    for (int nf = 0; nf < 4; nf++) {
                        MMA_BF16(acc[mf][nf], ah, bh[nf]);
                        MMA_BF16(acc[mf][nf], ah, bl[nf]);
                        MMA_BF16(acc[mf][nf], al, bh[nf]);
                    }
                }
            }
        }
        __syncthreads();
    }

    // epilogue
    int mrow = lane >> 2, ncol = (lane & 3) * 2;
#pragma unroll
    for (int mf = 0; mf < 4; mf++) {
#pragma unroll
        for (int nf = 0; nf < 4; nf++) {
            long gm = m0 + mw + mf * 16 + mrow;
            int gn = n0 + nw + nf * 8 + ncol;
            float v0 = acc[mf][nf][0], v1 = acc[mf][nf][1];
            float v2 = acc[mf][nf][2], v3 = acc[mf][nf][3];
            if (bias) {
                float b0 = bias[gn], b1 = bias[gn + 1];
                v0 += b0; v1 += b1; v2 += b0; v3 += b1;
            }
            if (relu) {
                v0 = fmaxf(v0, 0.f); v1 = fmaxf(v1, 0.f);
                v2 = fmaxf(v2, 0.f); v3 = fmaxf(v3, 0.f);
            }
            if (gm < M) {
                long o = coff + gm * (long)ldc + gn;
                if (Cf) *(float2*)&Cf[o] = make_float2(v0, v1);
                if (Chi) {
                    __nv_bfloat162 h, l;
                    bf16split(v0, h.x, l.x); bf16split(v1, h.y, l.y);
                    *(__nv_bfloat162*)&Chi[o] = h;
                    *(__nv_bfloat162*)&Clo[o] = l;
                }
            }
            if (gm + 8 < M) {
                long o = coff + (gm + 8) * (long)ldc + gn;
                if (Cf) *(float2*)&Cf[o] = make_float2(v2, v3);
                if (Chi) {
                    __nv_bfloat162 h, l;
                    bf16split(v2, h.x, l.x); bf16split(v3, h.y, l.y);
                    *(__nv_bfloat162*)&Chi[o] = h;
                    *(__nv_bfloat162*)&Clo[o] = l;
                }
            }
        }
    }
}

// ---------------- SYRK via mma.sync bf16 hi/lo: C = Z Z^T --------------------
__device__ __forceinline__ void ld_tile(char* smem, int off,
                                        const __nv_bfloat16* __restrict__ src,
                                        long row0, int r, int half) {
    long gr = row0 + r;
    uint4 v[8];
    if (gr < NTOT) {
        const uint4* s = reinterpret_cast<const uint4*>(src + gr * 128 + half * 64);
#pragma unroll
        for (int c = 0; c < 8; c++) v[c] = s[c];
    } else {
#pragma unroll
        for (int c = 0; c < 8; c++) v[c] = make_uint4(0, 0, 0, 0);
    }
    uint4* d = reinterpret_cast<uint4*>(smem + off + r * SY_PITCH_B + half * 128);
#pragma unroll
    for (int c = 0; c < 8; c++) d[c] = v[c];
}

__global__ __launch_bounds__(256, 1) void syrk_mma_kernel(float* __restrict__ C) {
    extern __shared__ char smem[];
    const int T = 94;
    int p = blockIdx.x;
    int ti = (int)((2.0 * T + 1.0 - sqrt((2.0 * T + 1.0) * (2.0 * T + 1.0) - 8.0 * p)) * 0.5);
    if (ti < 0) ti = 0;
    if (ti > T - 1) ti = T - 1;
    while (ti > 0 && ti * T - ti * (ti - 1) / 2 > p) ti--;
    while ((ti + 1) * T - ((ti + 1) * ti) / 2 <= p) ti++;
    int tj = ti + (p - (ti * T - ti * (ti - 1) / 2));
    long i0 = (long)ti * 128, j0 = (long)tj * 128;
    bool offdiag = (ti != tj);

    int tid = threadIdx.x, lane = tid & 31, wid = tid >> 5;

    {
        int r = tid >> 1, half = tid & 1;
        ld_tile(smem, 0,                 g_Zhi, i0, r, half);
        ld_tile(smem, SY_TILE_BYTES,     g_Zlo, i0, r, half);
        if (offdiag) {
            ld_tile(smem, 2 * SY_TILE_BYTES, g_Zhi, j0, r, half);
            ld_tile(smem, 3 * SY_TILE_BYTES, g_Zlo, j0, r, half);
        }
    }
    __syncthreads();

    uint32_t sb = smem_to_u32(smem);
    uint32_t offA_hi = 0, offA_lo = SY_TILE_BYTES;
    uint32_t offB_hi = offdiag ? 2u * SY_TILE_BYTES : 0u;
    uint32_t offB_lo = offdiag ? 3u * SY_TILE_BYTES : (uint32_t)SY_TILE_BYTES;

    int mw = (wid & 1) << 6;
    int nw = (wid >> 1) << 5;

    float acc[4][4][4];
#pragma unroll
    for (int a = 0; a < 4; a++)
#pragma unroll
        for (int b = 0; b < 4; b++)
#pragma unroll
            for (int c = 0; c < 4; c++) acc[a][b][c] = 0.f;

    int arow = mw + (lane & 15);
    uint32_t acol = ((uint32_t)(lane >> 4)) * 16u;
    int brow = nw + (lane & 7);
    uint32_t bcol = ((uint32_t)((lane >> 3) & 1)) * 16u;

#pragma unroll
    for (int ks = 0; ks < 8; ks++) {
        uint32_t kb = (uint32_t)ks * 32u;
        uint32_t bh[4][2], bl[4][2];
#pragma unroll
        for (int nf = 0; nf < 4; nf++) {
            uint32_t ro = (uint32_t)(brow + nf * 8) * SY_PITCH_B + kb + bcol;
            LDSM_X2(bh[nf], sb + offB_hi + ro);
            LDSM_X2(bl[nf], sb + offB_lo + ro);
        }
#pragma unroll
        for (int mf = 0; mf < 4; mf++) {
            uint32_t ro = (uint32_t)(arow + mf * 16) * SY_PITCH_B + kb + acol;
            uint32_t ah[4], al[4];
            LDSM_X4(ah, sb + offA_hi + ro);
            LDSM_X4(al, sb + offA_lo + ro);
#pragma unroll
            for (int nf = 0; nf < 4; nf++) {
                MMA_BF16(acc[mf][nf], ah, bh[nf]);
                MMA_BF16(acc[mf][nf], ah, bl[nf]);
                MMA_BF16(acc[mf][nf], al, bh[nf]);
            }
        }
    }
    __syncthreads();

    int mrow = lane >> 2, ncol = (lane & 3) * 2;
#pragma unroll
    for (int mf = 0; mf < 4; mf++) {
#pragma unroll
        for (int nf = 0; nf < 4; nf++) {
            long gm = i0 + mw + mf * 16 + mrow;
            long gn = j0 + nw + nf * 8 + ncol;
            if (gn < NTOT) {
                if (gm < NTOT)
                    *(float2*)&C[gm * (long)NTOT + gn] =
                        make_float2(acc[mf][nf][0], acc[mf][nf][1]);
                if (gm + 8 < NTOT)
                    *(float2*)&C[(gm + 8) * (long)NTOT + gn] =
                        make_float2(acc[mf][nf][2], acc[mf][nf][3]);
            }
        }
    }

    if (offdiag) {
        float* S = (float*)smem;   // [128][132]
#pragma unroll
        for (int mf = 0; mf < 4; mf++) {
#pragma unroll
            for (int nf = 0; nf < 4; nf++) {
                int ml = mw + mf * 16 + mrow;
                int nl = nw + nf * 8 + ncol;
                S[nl * 132 + ml]           = acc[mf][nf][0];
                S[(nl + 1) * 132 + ml]     = acc[mf][nf][1];
                S[nl * 132 + ml + 8]       = acc[mf][nf][2];
                S[(nl + 1) * 132 + ml + 8] = acc[mf][nf][3];
            }
        }
        __syncthreads();
        int rrow = tid >> 1, half = tid & 1;
        long gn = j0 + rrow;
        if (gn < NTOT) {
            const float* src = &S[rrow * 132 + half * 64];
            float* dst = &C[gn * (long)NTOT + i0 + half * 64];
#pragma unroll
            for (int q = 0; q < 16; q++) {
                long gm = i0 + half * 64 + q * 4;
                if (gm < NTOT) *(float4*)&dst[q * 4] = *(const float4*)&src[q * 4];
            }
        }
    }
}

// ---------------- host ----------------
extern "C" void kernel_launch(void* const* d_in, const int* in_sizes, int n_in,
                              void* d_out, int out_size) {
    const float* drug_x = (const float*)d_in[0];
    const int*   pro_x  = (const int*)d_in[1];
    const int*   arows  = (const int*)d_in[2];
    const int*   acols  = (const int*)d_in[3];
    const float* avals  = (const float*)d_in[4];
    const float* w1     = (const float*)d_in[5];
    const float* b1     = (const float*)d_in[6];
    const float* w2     = (const float*)d_in[7];
    const float* b2     = (const float*)d_in[8];
    const float* w3     = (const float*)d_in[9];
    const float* b3     = (const float*)d_in[10];
    const float* emb_xt = (const float*)d_in[11];
    const float* conv_w = (const float*)d_in[12];
    const float* conv_b = (const float*)d_in[13];
    const float* fc_w   = (const float*)d_in[14];
    const float* fc_b   = (const float*)d_in[15];
    const float* gc1_w  = (const float*)d_in[16];
    const float* gc2_w  = (const float*)d_in[17];
    const float* gc3_w  = (const float*)d_in[18];
    float* out = (float*)d_out;

    float *pM, *pXW1, *pHW;
    cudaGetSymbolAddress((void**)&pM,   g_M);
    cudaGetSymbolAddress((void**)&pXW1, g_XW1);
    cudaGetSymbolAddress((void**)&pHW,  g_HW);
    __nv_bfloat16 *pdxh,*pdxl,*pd1h,*pd1l,*pd2h,*pd2l,*pXh,*pXl,*pH1h,*pH1l;
    __nv_bfloat16 *pw1h,*pw1l,*pw2h,*pw2l,*pw3h,*pw3l,*pg1h,*pg1l,*pg23h,*pg23l;
    __nv_bfloat16 *pW2h,*pW2l,*pGth,*pGtl,*pZh,*pZl;
    cudaGetSymbolAddress((void**)&pdxh, g_dxhi);  cudaGetSymbolAddress((void**)&pdxl, g_dxlo);
    cudaGetSymbolAddress((void**)&pd1h, g_d1hi);  cudaGetSymbolAddress((void**)&pd1l, g_d1lo);
    cudaGetSymbolAddress((void**)&pd2h, g_d2hi);  cudaGetSymbolAddress((void**)&pd2l, g_d2lo);
    cudaGetSymbolAddress((void**)&pXh,  g_Xhi);   cudaGetSymbolAddress((void**)&pXl,  g_Xlo);
    cudaGetSymbolAddress((void**)&pH1h, g_H1hi);  cudaGetSymbolAddress((void**)&pH1l, g_H1lo);
    cudaGetSymbolAddress((void**)&pw1h, g_w1thi); cudaGetSymbolAddress((void**)&pw1l, g_w1tlo);
    cudaGetSymbolAddress((void**)&pw2h, g_w2thi); cudaGetSymbolAddress((void**)&pw2l, g_w2tlo);
    cudaGetSymbolAddress((void**)&pw3h, g_w3thi); cudaGetSymbolAddress((void**)&pw3l, g_w3tlo);
    cudaGetSymbolAddress((void**)&pg1h, g_gc1thi);cudaGetSymbolAddress((void**)&pg1l, g_gc1tlo);
    cudaGetSymbolAddress((void**)&pg23h,g_gc23thi);cudaGetSymbolAddress((void**)&pg23l,g_gc23tlo);
    cudaGetSymbolAddress((void**)&pW2h, g_W2dhi); cudaGetSymbolAddress((void**)&pW2l, g_W2dlo);
    cudaGetSymbolAddress((void**)&pGth, g_Gtthi); cudaGetSymbolAddress((void**)&pGtl, g_Gttlo);
    cudaGetSymbolAddress((void**)&pZh,  g_Zhi);   cudaGetSymbolAddress((void**)&pZl,  g_Zlo);

    static int smem_set = 0;
    if (!smem_set) {
        cudaFuncSetAttribute(syrk_mma_kernel, cudaFuncAttributeMaxDynamicSharedMemorySize,
                             SY_SMEM_TOTAL);
        cudaFuncSetAttribute(gemm_mma_kernel, cudaFuncAttributeMaxDynamicSharedMemorySize,
                             SY_SMEM_TOTAL);
        smem_set = 1;
    }

    // CSR build
    zero_cnt_kernel<<<47, 256>>>();
    count_kernel<<<750, 256>>>(arows);
    scan_kernel<<<1, 1024>>>();
    scatter_kernel<<<750, 256>>>(arows, acols, avals);

    // splits / repacks
    dxsplit_kernel<<<(N_DRUG * 176 + 255) / 256, 256>>>(drug_x);
    tsplit_kernel<<<88, 256>>>(w1, 167, 128, 176, pw1h, pw1l);
    tsplit_kernel<<<128, 256>>>(w2, 128, 256, 128, pw2h, pw2l);
    tsplit_kernel<<<128, 256>>>(w3, 256, 128, 256, pw3h, pw3l);
    tsplit_kernel<<<128, 256>>>(gc1_w, 128, 256, 128, pg1h, pg1l);
    tsplit23_kernel<<<256, 256>>>(gc2_w, gc3_w);
    repack_w_kernel<<<1000, 256>>>(conv_w);
    g_kernel<<<26 * 256, 128>>>(emb_xt, fc_w);
    pbias_kernel<<<1, 128>>>(fc_b, conv_b, fc_w);

    // drug MLP (tensor cores)
    gemm_mma_kernel<<<dim3(1, 86, 1), 256, SY_SMEM_TOTAL>>>(
        pdxh, pdxl, 176, pw1h, pw1l, 176, b1,
        nullptr, pd1h, pd1l, 128, N_DRUG, 128, 176, 1, 0, 0);
    gemm_mma_kernel<<<dim3(2, 86, 1), 256, SY_SMEM_TOTAL>>>(
        pd1h, pd1l, 128, pw2h, pw2l, 128, b2,
        nullptr, pd2h, pd2l, 256, N_DRUG, 256, 128, 1, 0, 0);
    gemm_mma_kernel<<<dim3(1, 86, 1), 256, SY_SMEM_TOTAL>>>(
        pd2h, pd2l, 256, pw3h, pw3l, 256, b3,
        nullptr, pXh, pXl, 128, N_DRUG, 128, 256, 1, 0, 0);

    // protein: M[t] = W2d @ Gt[t]  (batched, tensor cores)
    gemm_mma_kernel<<<dim3(1, 8, 26), 256, SY_SMEM_TOTAL>>>(
        pW2h, pW2l, 256, pGth, pGtl, 256, nullptr,
        pM, nullptr, nullptr, 128, N_PRO, 128, 256, 0,
        128L * 256, (long)N_PRO * 128);
    protein_gather_kernel<<<1000, 128>>>(pro_x);

    // GCN encoder
    gemm_mma_kernel<<<dim3(2, 94, 1), 256, SY_SMEM_TOTAL>>>(
        pXh, pXl, 128, pg1h, pg1l, 128, nullptr,
        pXW1, nullptr, nullptr, 256, NTOT, 256, 128, 0, 0, 0);
    spmm256_kernel<<<NTOT, 256>>>(pXW1, nullptr, nullptr, pH1h, pH1l, 1, 0);
    gemm_mma_kernel<<<dim3(2, 94, 1), 256, SY_SMEM_TOTAL>>>(
        pH1h, pH1l, 256, pg23h, pg23l, 256, nullptr,
        pHW, nullptr, nullptr, 256, NTOT, 256, 256, 0, 0, 0);
    spmm256_kernel<<<NTOT, 256>>>(pHW, out + OFF_MU, out + OFF_LV, pZh, pZl, 0, 1);

    // decoder: adj_rec = Z Z^T (mma.sync bf16 hi/lo split)
    syrk_mma_kernel<<<4465, 256, SY_SMEM_TOTAL>>>(out);
}

// round 7
// speedup vs baseline: 1.5474x; 1.2151x over previous
#include <cuda_runtime.h>
#include <cuda_bf16.h>
#include <math.h>
#include <stdint.h>

#define N_DRUG 11000
#define N_PRO  1000
#define NTOT   12000
#define NE     192000
#define OFF_MU 144000000L
#define OFF_LV 145536000L

// ---------------- static scratch (no allocations allowed) ----------------
__device__ float g_M[26L*N_PRO*128];
__device__ float g_pbias[128];
__device__ float g_XW1[NTOT*256];
__device__ float g_HW[NTOT*256];
__device__ int   g_cnt[NTOT];
__device__ int   g_rp[NTOT+1];
__device__ int   g_cur[NTOT];
__device__ int   g_ccol[NE];
__device__ float g_cval[NE];
__device__ __nv_bfloat16 g_Zhi[NTOT*128];
__device__ __nv_bfloat16 g_Zlo[NTOT*128];
// bf16 hi/lo activations
__device__ __nv_bfloat16 g_dxhi[N_DRUG*176], g_dxlo[N_DRUG*176];
__device__ __nv_bfloat16 g_d1hi[N_DRUG*128], g_d1lo[N_DRUG*128];
__device__ __nv_bfloat16 g_d2hi[N_DRUG*256], g_d2lo[N_DRUG*256];
__device__ __nv_bfloat16 g_Xhi[NTOT*128],    g_Xlo[NTOT*128];
__device__ __nv_bfloat16 g_H1hi[NTOT*256],   g_H1lo[NTOT*256];
// bf16 hi/lo transposed weights
__device__ __nv_bfloat16 g_w1thi[128*176],  g_w1tlo[128*176];
__device__ __nv_bfloat16 g_w2thi[256*128],  g_w2tlo[256*128];
__device__ __nv_bfloat16 g_w3thi[128*256],  g_w3tlo[128*256];
__device__ __nv_bfloat16 g_gc1thi[256*128], g_gc1tlo[256*128];
__device__ __nv_bfloat16 g_gc23thi[256*256],g_gc23tlo[256*256];
__device__ __nv_bfloat16 g_W2dhi[N_PRO*256],g_W2dlo[N_PRO*256];
__device__ __nv_bfloat16 g_Gtthi[26L*128*256], g_Gttlo[26L*128*256];

__device__ __forceinline__ uint32_t smem_to_u32(const void* smem_ptr) {
    uint32_t addr;
    asm("{ .reg .u64 tmp; cvta.to.shared.u64 tmp, %1; cvt.u32.u64 %0, tmp; }"
        : "=r"(addr) : "l"(smem_ptr));
    return addr;
}

// ---------------- warp-level tensor-core primitives (sm_80+ baseline PTX) ----
#define LDSM_X4(r, addr) \
    asm volatile("ldmatrix.sync.aligned.m8n8.x4.shared.b16 {%0,%1,%2,%3}, [%4];" \
        : "=r"((r)[0]), "=r"((r)[1]), "=r"((r)[2]), "=r"((r)[3]) : "r"(addr))
#define LDSM_X2(r, addr) \
    asm volatile("ldmatrix.sync.aligned.m8n8.x2.shared.b16 {%0,%1}, [%2];" \
        : "=r"((r)[0]), "=r"((r)[1]) : "r"(addr))
#define MMA_BF16(c, a, b) \
    asm volatile("mma.sync.aligned.m16n8k16.row.col.f32.bf16.bf16.f32 " \
        "{%0,%1,%2,%3}, {%4,%5,%6,%7}, {%8,%9}, {%0,%1,%2,%3};" \
        : "+f"((c)[0]), "+f"((c)[1]), "+f"((c)[2]), "+f"((c)[3]) \
        : "r"((a)[0]), "r"((a)[1]), "r"((a)[2]), "r"((a)[3]), \
          "r"((b)[0]), "r"((b)[1]))

#define SY_PITCH_B 272
#define SY_TILE_BYTES (128 * SY_PITCH_B)          // 34816
#define GM_SMEM_TOTAL (4 * SY_TILE_BYTES)         // 139264 (gemm)
#define SY_SMEM_TOTAL (6 * SY_TILE_BYTES)         // 208896 (syrk, paired j)

__device__ __forceinline__ void bf16split(float v, __nv_bfloat16& h, __nv_bfloat16& l) {
    h = __float2bfloat16(v);
    l = __float2bfloat16(v - __bfloat162float(h));
}

// ---------------- CSR build ----------------
__global__ void count_kernel(const int* __restrict__ rows) {
    int e = blockIdx.x * 256 + threadIdx.x;
    if (e < NE) atomicAdd(&g_cnt[rows[e]], 1);
}
__global__ void scan_kernel() {
    __shared__ int sums[1024];
    int tid = threadIdx.x;
    const int CH = (NTOT + 1023) / 1024;   // 12
    int base = tid * CH;
    int s = 0;
    for (int i = 0; i < CH; i++) { int idx = base + i; if (idx < NTOT) s += g_cnt[idx]; }
    sums[tid] = s;
    __syncthreads();
    for (int off = 1; off < 1024; off <<= 1) {
        int v = 0;
        if (tid >= off) v = sums[tid - off];
        __syncthreads();
        sums[tid] += v;
        __syncthreads();
    }
    int prefix = (tid == 0) ? 0 : sums[tid - 1];
    for (int i = 0; i < CH; i++) {
        int idx = base + i;
        if (idx < NTOT) { g_rp[idx] = prefix; g_cur[idx] = prefix; prefix += g_cnt[idx]; }
    }
    if (tid == 1023) g_rp[NTOT] = NE;
}
__global__ void scatter_kernel(const int* __restrict__ rows, const int* __restrict__ cols,
                               const float* __restrict__ vals) {
    int e = blockIdx.x * 256 + threadIdx.x;
    if (e < NE) {
        int r = rows[e];
        int pos = atomicAdd(&g_cur[r], 1);
        g_ccol[pos] = cols[e];
        g_cval[pos] = vals[e];
    }
}

// ---------------- merged prep kernel (all weight splits/repacks) -------------
// block ranges:
#define PS0 7563                 // dxsplit       (11000*176/256)
#define PS1 (PS0 + 88)           // w1t
#define PS2 (PS1 + 128)          // w2t
#define PS3 (PS2 + 128)          // w3t
#define PS4 (PS3 + 128)          // gc1t
#define PS5 (PS4 + 256)          // gc23t
#define PS6 (PS5 + 1000)         // repack conv_w
#define PS7 (PS6 + 3328)         // G (26*256 slices, 2 per block)
#define PS8 (PS7 + 1)            // pbias
__device__ __forceinline__ void prep_tsplit(int lidx, const float* __restrict__ W,
                                            int K, int N, int ldt,
                                            __nv_bfloat16* Thi, __nv_bfloat16* Tlo) {
    if (lidx < N * ldt) {
        int n = lidx / ldt, k = lidx - n * ldt;
        float v = (k < K) ? W[(long)k * N + n] : 0.f;
        bf16split(v, Thi[lidx], Tlo[lidx]);
    }
}
__global__ void prep_kernel(const float* __restrict__ dx,
                            const float* __restrict__ w1, const float* __restrict__ w2,
                            const float* __restrict__ w3, const float* __restrict__ gc1,
                            const float* __restrict__ gc2, const float* __restrict__ gc3,
                            const float* __restrict__ conv_w,
                            const float* __restrict__ emb, const float* __restrict__ fc_w,
                            const float* __restrict__ fc_b, const float* __restrict__ conv_b) {
    int b = blockIdx.x, tid = threadIdx.x;
    if (b < PS0) {
        int idx = b * 256 + tid;
        if (idx < N_DRUG * 176) {
            int row = idx / 176, col = idx - row * 176;
            float v = (col < 167) ? dx[(long)row * 167 + col] : 0.f;
            bf16split(v, g_dxhi[idx], g_dxlo[idx]);
        }
    } else if (b < PS1) {
        prep_tsplit((b - PS0) * 256 + tid, w1, 167, 128, 176, g_w1thi, g_w1tlo);
    } else if (b < PS2) {
        prep_tsplit((b - PS1) * 256 + tid, w2, 128, 256, 128, g_w2thi, g_w2tlo);
    } else if (b < PS3) {
        prep_tsplit((b - PS2) * 256 + tid, w3, 256, 128, 256, g_w3thi, g_w3tlo);
    } else if (b < PS4) {
        prep_tsplit((b - PS3) * 256 + tid, gc1, 128, 256, 128, g_gc1thi, g_gc1tlo);
    } else if (b < PS5) {
        int idx = (b - PS4) * 256 + tid;   // n*256 + k
        int n = idx >> 8, k = idx & 255;
        float v = (n < 128) ? gc2[k * 128 + n] : gc3[k * 128 + n - 128];
        bf16split(v, g_gc23thi[idx], g_gc23tlo[idx]);
    } else if (b < PS6) {
        int idx = (b - PS5) * 256 + tid;
        if (idx < N_PRO * 256) {
            int i = idx >> 8, ok = idx & 255;
            int o = ok >> 3, k = ok & 7;
            float v = conv_w[((long)o * N_PRO + i) * 8 + k];
            bf16split(v, g_W2dhi[idx], g_W2dlo[idx]);
        }
    } else if (b < PS7) {
        // Gtt[t][f][ok] = sum_h emb[t, h+kk] * fc_w[(o*121+h)*128 + f]
        __shared__ float e[2][128];
        int half = tid >> 7, f = tid & 127;
        int idx2 = (b - PS6) * 2 + half;          // t*256 + ok
        int t = idx2 >> 8, ok = idx2 & 255;
        int o = ok >> 3, kk = ok & 7;
        if (f < 121) e[half][f] = emb[t * 128 + kk + f];
        __syncthreads();
        float acc = 0.f;
#pragma unroll 4
        for (int h = 0; h < 121; h++)
            acc += e[half][h] * fc_w[(o * 121 + h) * 128 + f];
        long dst = ((long)t * 128 + f) * 256 + ok;
        bf16split(acc, g_Gtthi[dst], g_Gttlo[dst]);
    } else {
        int f = tid;
        if (f < 128) {
            float acc = fc_b[f];
            for (int o = 0; o < 32; o++) {
                float cb = conv_b[o];
                for (int h = 0; h < 121; h++) acc += cb * fc_w[(o * 121 + h) * 128 + f];
            }
            g_pbias[f] = acc;
        }
    }
}

__global__ void protein_gather_kernel(const int* __restrict__ pro_x) {
    int p = blockIdx.x, f = threadIdx.x;   // 1000 blocks x 128
    __shared__ int tok[128];
    float acc = g_pbias[f];
    for (int c = 0; c < 1000; c += 128) {
        int n = min(128, 1000 - c);
        if (f < n) tok[f] = pro_x[p * 1000 + c + f];
        __syncthreads();
#pragma unroll 8
        for (int ii = 0; ii < n; ii++) {
            int t = tok[ii];
            acc += g_M[((long)t * N_PRO + c + ii) * 128 + f];
        }
        __syncthreads();
    }
    long dst = (long)(N_DRUG + p) * 128 + f;
    bf16split(acc, g_Xhi[dst], g_Xlo[dst]);
}

// ---------------- SpMM (CSR gather), F=256 ----------------------------------
__global__ void spmm256_kernel(const float* __restrict__ Xin,
                               float* __restrict__ out1, float* __restrict__ out2,
                               __nv_bfloat16* __restrict__ bh, __nv_bfloat16* __restrict__ bl,
                               int relu, int split128) {
    int r = blockIdx.x;
    int f = threadIdx.x;   // 256
    int e0 = g_rp[r], e1 = g_rp[r + 1];
    float acc = 0.f;
    for (int e = e0; e < e1; e++) {
        int c = g_ccol[e];
        float v = g_cval[e];
        acc += v * Xin[(long)c * 256 + f];
    }
    if (relu) acc = fmaxf(acc, 0.f);
    if (split128) {
        if (f < 128) {
            out1[(long)r * 128 + f] = acc;
            bf16split(acc, bh[(long)r * 128 + f], bl[(long)r * 128 + f]);
        } else {
            out2[(long)r * 128 + f - 128] = acc;
        }
    } else {
        bf16split(acc, bh[(long)r * 256 + f], bl[(long)r * 256 + f]);
    }
}

// ---------------- tensor-core GEMM: C[M,N] = A[M,K] @ Bt[N,K]^T --------------
__global__ __launch_bounds__(256, 1) void gemm_mma_kernel(
    const __nv_bfloat16* __restrict__ Ahi, const __nv_bfloat16* __restrict__ Alo, int lda,
    const __nv_bfloat16* __restrict__ Bhi, const __nv_bfloat16* __restrict__ Blo, int ldb,
    const float* __restrict__ bias,
    float* __restrict__ Cf, __nv_bfloat16* __restrict__ Chi, __nv_bfloat16* __restrict__ Clo,
    int ldc, int M, int N, int K, int relu, long sB, long sC)
{
    Bhi += (long)blockIdx.z * sB;
    Blo += (long)blockIdx.z * sB;
    long coff = (long)blockIdx.z * sC;
    extern __shared__ char smem[];
    uint32_t sb = smem_to_u32(smem);

    int tid = threadIdx.x, lane = tid & 31, wid = tid >> 5;
    int m0 = blockIdx.y * 128, n0 = blockIdx.x * 128;

    int mw = (wid & 1) << 6;
    int nw = (wid >> 1) << 5;
    float acc[4][4][4];
#pragma unroll
    for (int a = 0; a < 4; a++)
#pragma unroll
        for (int b = 0; b < 4; b++)
#pragma unroll
            for (int c = 0; c < 4; c++) acc[a][b][c] = 0.f;

    int arow = mw + (lane & 15);
    uint32_t acol = ((uint32_t)(lane >> 4)) * 16u;
    int brow = nw + (lane & 7);
    uint32_t bcol = ((uint32_t)((lane >> 3) & 1)) * 16u;

    int r = tid >> 1, half = tid & 1;

    for (int k0 = 0; k0 < K; k0 += 128) {
        {
            const __nv_bfloat16* srcs[4] = {Ahi, Alo, Bhi, Blo};
            int lds[4]   = {lda, lda, ldb, ldb};
            int base[4]  = {m0, m0, n0, n0};
            int limit[4] = {M, M, N, N};
#pragma unroll
            for (int tI = 0; tI < 4; tI++) {
                long gr = (long)base[tI] + r;
                bool rv = gr < limit[tI];
                const __nv_bfloat16* sp = srcs[tI] + gr * (long)lds[tI] + k0 + half * 64;
                uint4* d = (uint4*)(smem + tI * SY_TILE_BYTES + r * SY_PITCH_B + half * 128);
#pragma unroll
                for (int c = 0; c < 8; c++) {
                    int col0 = half * 64 + c * 8;
                    uint4 v = make_uint4(0, 0, 0, 0);
                    if (rv && (k0 + col0 + 8) <= K) v = *(const uint4*)(sp + c * 8);
                    d[c] = v;
                }
            }
        }
        __syncthreads();

        int ksteps = (K - k0) >= 128 ? 8 : ((K - k0 + 15) >> 4);
        uint32_t offA_hi = 0, offA_lo = SY_TILE_BYTES;
        uint32_t offB_hi = 2u * SY_TILE_BYTES, offB_lo = 3u * SY_TILE_BYTES;
        for (int ks = 0; ks < ksteps; ks++) {
            uint32_t kb = (uint32_t)ks * 32u;
            uint32_t bh[4][2], bl[4][2];
#pragma unroll
            for (int nf = 0; nf < 4; nf++) {
                uint32_t ro = (uint32_t)(brow + nf * 8) * SY_PITCH_B + kb + bcol;
                LDSM_X2(bh[nf], sb + offB_hi + ro);
                LDSM_X2(bl[nf], sb + offB_lo + ro);
            }
#pragma unroll
            for (int mf = 0; mf < 4; mf++) {
                uint32_t ro = (uint32_t)(arow + mf * 16) * SY_PITCH_B + kb + acol;
                uint32_t ah[4], al[4];
                LDSM_X4(ah, sb + offA_hi + ro);
                LDSM_X4(al, sb + offA_lo + ro);
#pragma unroll
                for (int nf = 0; nf < 4; nf++) {
                    MMA_BF16(acc[mf][nf], ah, bh[nf]);
                    MMA_BF16(acc[mf][nf], ah, bl[nf]);
                    MMA_BF16(acc[mf][nf], al, bh[nf]);
                }
            }
        }
        __syncthreads();
    }

    // epilogue
    int mrow = lane >> 2, ncol = (lane & 3) * 2;
#pragma unroll
    for (int mf = 0; mf < 4; mf++) {
#pragma unroll
        for (int nf = 0; nf < 4; nf++) {
            long gm = m0 + mw + mf * 16 + mrow;
            int gn = n0 + nw + nf * 8 + ncol;
            float v0 = acc[mf][nf][0], v1 = acc[mf][nf][1];
            float v2 = acc[mf][nf][2], v3 = acc[mf][nf][3];
            if (bias) {
                float b0 = bias[gn], b1 = bias[gn + 1];
                v0 += b0; v1 += b1; v2 += b0; v3 += b1;
            }
            if (relu) {
                v0 = fmaxf(v0, 0.f); v1 = fmaxf(v1, 0.f);
                v2 = fmaxf(v2, 0.f); v3 = fmaxf(v3, 0.f);
            }
            if (gm < M) {
                long o = coff + gm * (long)ldc + gn;
                if (Cf) *(float2*)&Cf[o] = make_float2(v0, v1);
                if (Chi) {
                    __nv_bfloat162 h, l;
                    bf16split(v0, h.x, l.x); bf16split(v1, h.y, l.y);
                    *(__nv_bfloat162*)&Chi[o] = h;
                    *(__nv_bfloat162*)&Clo[o] = l;
                }
            }
            if (gm + 8 < M) {
                long o = coff + (gm + 8) * (long)ldc + gn;
                if (Cf) *(float2*)&Cf[o] = make_float2(v2, v3);
                if (Chi) {
                    __nv_bfloat162 h, l;
                    bf16split(v2, h.x, l.x); bf16split(v3, h.y, l.y);
                    *(__nv_bfloat162*)&Chi[o] = h;
                    *(__nv_bfloat162*)&Clo[o] = l;
                }
            }
        }
    }
}

// ---------------- SYRK via mma.sync bf16 hi/lo: C = Z Z^T --------------------
// Paired-j: one CTA handles tiles (i,j0) and (i,j0+1). Smem: 6 tiles.
__device__ __forceinline__ void ld_tile(char* smem, int off,
                                        const __nv_bfloat16* __restrict__ src,
                                        long row0, int r, int half) {
    long gr = row0 + r;
    uint4 v[8];
    if (gr < NTOT) {
        const uint4* s = reinterpret_cast<const uint4*>(src + gr * 128 + half * 64);
#pragma unroll
        for (int c = 0; c < 8; c++) v[c] = s[c];
    } else {
#pragma unroll
        for (int c = 0; c < 8; c++) v[c] = make_uint4(0, 0, 0, 0);
    }
    uint4* d = reinterpret_cast<uint4*>(smem + off + r * SY_PITCH_B + half * 128);
#pragma unroll
    for (int c = 0; c < 8; c++) d[c] = v[c];
}

__device__ __forceinline__ void syrk_tile(uint32_t sb, uint32_t offBh, uint32_t offBl,
                                          long i0, long j0, bool mirror,
                                          float* __restrict__ C, int lane, int wid) {
    int mw = (wid & 1) << 6;
    int nw = (wid >> 1) << 5;
    float acc[4][4][4];
#pragma unroll
    for (int a = 0; a < 4; a++)
#pragma unroll
        for (int b = 0; b < 4; b++)
#pragma unroll
            for (int c = 0; c < 4; c++) acc[a][b][c] = 0.f;

    int arow = mw + (lane & 15);
    uint32_t acol = ((uint32_t)(lane >> 4)) * 16u;
    int brow = nw + (lane & 7);
    uint32_t bcol = ((uint32_t)((lane >> 3) & 1)) * 16u;

#pragma unroll
    for (int ks = 0; ks < 8; ks++) {
        uint32_t kb = (uint32_t)ks * 32u;
        uint32_t bh[4][2], bl[4][2];
#pragma unroll
        for (int nf = 0; nf < 4; nf++) {
            uint32_t ro = (uint32_t)(brow + nf * 8) * SY_PITCH_B + kb + bcol;
            LDSM_X2(bh[nf], sb + offBh + ro);
            LDSM_X2(bl[nf], sb + offBl + ro);
        }
#pragma unroll
        for (int mf = 0; mf < 4; mf++) {
            uint32_t ro = (uint32_t)(arow + mf * 16) * SY_PITCH_B + kb + acol;
            uint32_t ah[4], al[4];
            LDSM_X4(ah, sb + 0 + ro);
            LDSM_X4(al, sb + SY_TILE_BYTES + ro);
#pragma unroll
            for (int nf = 0; nf < 4; nf++) {
                MMA_BF16(acc[mf][nf], ah, bh[nf]);
                MMA_BF16(acc[mf][nf], ah, bl[nf]);
                MMA_BF16(acc[mf][nf], al, bh[nf]);
            }
        }
    }

    int mrow = lane >> 2, ncol = (lane & 3) * 2;
#pragma unroll
    for (int mf = 0; mf < 4; mf++) {
#pragma unroll
        for (int nf = 0; nf < 4; nf++) {
            long gm = i0 + mw + mf * 16 + mrow;
            long gn = j0 + nw + nf * 8 + ncol;
            float v0 = acc[mf][nf][0], v1 = acc[mf][nf][1];
            float v2 = acc[mf][nf][2], v3 = acc[mf][nf][3];
            if (gn < NTOT) {
                if (gm < NTOT)
                    *(float2*)&C[gm * (long)NTOT + gn] = make_float2(v0, v1);
                if (gm + 8 < NTOT)
                    *(float2*)&C[(gm + 8) * (long)NTOT + gn] = make_float2(v2, v3);
            }
            if (mirror) {
                // transposed store: 32B-sector aligned groups across the warp
                if (gn < NTOT) {
                    if (gm < NTOT)      C[gn * (long)NTOT + gm] = v0;
                    if (gm + 8 < NTOT)  C[gn * (long)NTOT + gm + 8] = v2;
                }
                if (gn + 1 < NTOT) {
                    if (gm < NTOT)      C[(gn + 1) * (long)NTOT + gm] = v1;
                    if (gm + 8 < NTOT)  C[(gn + 1) * (long)NTOT + gm + 8] = v3;
                }
            }
        }
    }
}

__global__ __launch_bounds__(256, 1) void syrk_mma_kernel(float* __restrict__ C) {
    extern __shared__ char smem[];
    // map blockIdx -> (i, pair q): row i has ceil((94-i)/2) pairs; total 2256
    int rem = blockIdx.x;
    int i = 0;
    while (true) {
        int np = (95 - i) >> 1;
        if (rem < np) break;
        rem -= np;
        i++;
    }
    int j0 = i + 2 * rem;
    int j1 = j0 + 1;
    bool has2 = (j1 <= 93);
    long i0 = (long)i * 128, jj0 = (long)j0 * 128, jj1 = (long)j1 * 128;

    int tid = threadIdx.x, lane = tid & 31, wid = tid >> 5;

    {
        int r = tid >> 1, half = tid & 1;
        ld_tile(smem, 0,                 g_Zhi, i0, r, half);
        ld_tile(smem, SY_TILE_BYTES,     g_Zlo, i0, r, half);
        ld_tile(smem, 2 * SY_TILE_BYTES, g_Zhi, jj0, r, half);
        ld_tile(smem, 3 * SY_TILE_BYTES, g_Zlo, jj0, r, half);
        if (has2) {
            ld_tile(smem, 4 * SY_TILE_BYTES, g_Zhi, jj1, r, half);
            ld_tile(smem, 5 * SY_TILE_BYTES, g_Zlo, jj1, r, half);
        }
    }
    __syncthreads();

    uint32_t sb = smem_to_u32(smem);
    syrk_tile(sb, 2u * SY_TILE_BYTES, 3u * SY_TILE_BYTES, i0, jj0, j0 != i, C, lane, wid);
    if (has2)
        syrk_tile(sb, 4u * SY_TILE_BYTES, 5u * SY_TILE_BYTES, i0, jj1, true, C, lane, wid);
}

// ---------------- host ----------------
extern "C" void kernel_launch(void* const* d_in, const int* in_sizes, int n_in,
                              void* d_out, int out_size) {
    const float* drug_x = (const float*)d_in[0];
    const int*   pro_x  = (const int*)d_in[1];
    const int*   arows  = (const int*)d_in[2];
    const int*   acols  = (const int*)d_in[3];
    const float* avals  = (const float*)d_in[4];
    const float* w1     = (const float*)d_in[5];
    const float* b1     = (const float*)d_in[6];
    const float* w2     = (const float*)d_in[7];
    const float* b2     = (const float*)d_in[8];
    const float* w3     = (const float*)d_in[9];
    const float* b3     = (const float*)d_in[10];
    const float* emb_xt = (const float*)d_in[11];
    const float* conv_w = (const float*)d_in[12];
    const float* conv_b = (const float*)d_in[13];
    const float* fc_w   = (const float*)d_in[14];
    const float* fc_b   = (const float*)d_in[15];
    const float* gc1_w  = (const float*)d_in[16];
    const float* gc2_w  = (const float*)d_in[17];
    const float* gc3_w  = (const float*)d_in[18];
    float* out = (float*)d_out;

    float *pM, *pXW1, *pHW;
    int *pcnt;
    cudaGetSymbolAddress((void**)&pM,   g_M);
    cudaGetSymbolAddress((void**)&pXW1, g_XW1);
    cudaGetSymbolAddress((void**)&pHW,  g_HW);
    cudaGetSymbolAddress((void**)&pcnt, g_cnt);
    __nv_bfloat16 *pdxh,*pdxl,*pd1h,*pd1l,*pd2h,*pd2l,*pXh,*pXl,*pH1h,*pH1l;
    __nv_bfloat16 *pw1h,*pw1l,*pw2h,*pw2l,*pw3h,*pw3l,*pg1h,*pg1l,*pg23h,*pg23l;
    __nv_bfloat16 *pW2h,*pW2l,*pGth,*pGtl,*pZh,*pZl;
    cudaGetSymbolAddress((void**)&pdxh, g_dxhi);  cudaGetSymbolAddress((void**)&pdxl, g_dxlo);
    cudaGetSymbolAddress((void**)&pd1h, g_d1hi);  cudaGetSymbolAddress((void**)&pd1l, g_d1lo);
    cudaGetSymbolAddress((void**)&pd2h, g_d2hi);  cudaGetSymbolAddress((void**)&pd2l, g_d2lo);
    cudaGetSymbolAddress((void**)&pXh,  g_Xhi);   cudaGetSymbolAddress((void**)&pXl,  g_Xlo);
    cudaGetSymbolAddress((void**)&pH1h, g_H1hi);  cudaGetSymbolAddress((void**)&pH1l, g_H1lo);
    cudaGetSymbolAddress((void**)&pw1h, g_w1thi); cudaGetSymbolAddress((void**)&pw1l, g_w1tlo);
    cudaGetSymbolAddress((void**)&pw2h, g_w2thi); cudaGetSymbolAddress((void**)&pw2l, g_w2tlo);
    cudaGetSymbolAddress((void**)&pw3h, g_w3thi); cudaGetSymbolAddress((void**)&pw3l, g_w3tlo);
    cudaGetSymbolAddress((void**)&pg1h, g_gc1thi);cudaGetSymbolAddress((void**)&pg1l, g_gc1tlo);
    cudaGetSymbolAddress((void**)&pg23h,g_gc23thi);cudaGetSymbolAddress((void**)&pg23l,g_gc23tlo);
    cudaGetSymbolAddress((void**)&pW2h, g_W2dhi); cudaGetSymbolAddress((void**)&pW2l, g_W2dlo);
    cudaGetSymbolAddress((void**)&pGth, g_Gtthi); cudaGetSymbolAddress((void**)&pGtl, g_Gttlo);
    cudaGetSymbolAddress((void**)&pZh,  g_Zhi);   cudaGetSymbolAddress((void**)&pZl,  g_Zlo);

    static int smem_set = 0;
    if (!smem_set) {
        cudaFuncSetAttribute(syrk_mma_kernel, cudaFuncAttributeMaxDynamicSharedMemorySize,
                             SY_SMEM_TOTAL);
        cudaFuncSetAttribute(gemm_mma_kernel, cudaFuncAttributeMaxDynamicSharedMemorySize,
                             GM_SMEM_TOTAL);
        smem_set = 1;
    }

    // CSR build
    cudaMemsetAsync(pcnt, 0, NTOT * sizeof(int));
    count_kernel<<<750, 256>>>(arows);
    scan_kernel<<<1, 1024>>>();
    scatter_kernel<<<750, 256>>>(arows, acols, avals);

    // merged prep (all splits/repacks/G/pbias)
    prep_kernel<<<PS8, 256>>>(drug_x, w1, w2, w3, gc1_w, gc2_w, gc3_w,
                              conv_w, emb_xt, fc_w, fc_b, conv_b);

    // drug MLP (tensor cores)
    gemm_mma_kernel<<<dim3(1, 86, 1), 256, GM_SMEM_TOTAL>>>(
        pdxh, pdxl, 176, pw1h, pw1l, 176, b1,
        nullptr, pd1h, pd1l, 128, N_DRUG, 128, 176, 1, 0, 0);
    gemm_mma_kernel<<<dim3(2, 86, 1), 256, GM_SMEM_TOTAL>>>(
        pd1h, pd1l, 128, pw2h, pw2l, 128, b2,
        nullptr, pd2h, pd2l, 256, N_DRUG, 256, 128, 1, 0, 0);
    gemm_mma_kernel<<<dim3(1, 86, 1), 256, GM_SMEM_TOTAL>>>(
        pd2h, pd2l, 256, pw3h, pw3l, 256, b3,
        nullptr, pXh, pXl, 128, N_DRUG, 128, 256, 1, 0, 0);

    // protein: M[t] = W2d @ Gt[t]  (batched, tensor cores)
    gemm_mma_kernel<<<dim3(1, 8, 26), 256, GM_SMEM_TOTAL>>>(
        pW2h, pW2l, 256, pGth, pGtl, 256, nullptr,
        pM, nullptr, nullptr, 128, N_PRO, 128, 256, 0,
        128L * 256, (long)N_PRO * 128);
    protein_gather_kernel<<<1000, 128>>>(pro_x);

    // GCN encoder
    gemm_mma_kernel<<<dim3(2, 94, 1), 256, GM_SMEM_TOTAL>>>(
        pXh, pXl, 128, pg1h, pg1l, 128, nullptr,
        pXW1, nullptr, nullptr, 256, NTOT, 256, 128, 0, 0, 0);
    spmm256_kernel<<<NTOT, 256>>>(pXW1, nullptr, nullptr, pH1h, pH1l, 1, 0);
    gemm_mma_kernel<<<dim3(2, 94, 1), 256, GM_SMEM_TOTAL>>>(
        pH1h, pH1l, 256, pg23h, pg23l, 256, nullptr,
        pHW, nullptr, nullptr, 256, NTOT, 256, 256, 0, 0, 0);
    spmm256_kernel<<<NTOT, 256>>>(pHW, out + OFF_MU, out + OFF_LV, pZh, pZl, 0, 1);

    // decoder: adj_rec = Z Z^T (paired-j tiles)
    syrk_mma_kernel<<<2256, 256, SY_SMEM_TOTAL>>>(out);
}

// round 8
// speedup vs baseline: 1.5604x; 1.0084x over previous
#include <cuda_runtime.h>
#include <cuda_bf16.h>
#include <cuda_fp16.h>
#include <math.h>
#include <stdint.h>

#define N_DRUG 11000
#define N_PRO  1000
#define NTOT   12000
#define NE     192000
#define OFF_MU 144000000L
#define OFF_LV 145536000L

// ---------------- static scratch (no allocations allowed) ----------------
__device__ __half g_M16[26L*N_PRO*128];
__device__ float g_pbias[128];
__device__ float g_XW1[NTOT*256];
__device__ float g_HW[NTOT*256];
__device__ int   g_cnt[NTOT];
__device__ int   g_rp[NTOT+1];
__device__ int   g_cur[NTOT];
__device__ int   g_ccol[NE];
__device__ float g_cval[NE];
__device__ __nv_bfloat16 g_Zhi[NTOT*128];
__device__ __nv_bfloat16 g_Zlo[NTOT*128];
// bf16 hi/lo activations
__device__ __nv_bfloat16 g_dxhi[N_DRUG*176], g_dxlo[N_DRUG*176];
__device__ __nv_bfloat16 g_d1hi[N_DRUG*128], g_d1lo[N_DRUG*128];
__device__ __nv_bfloat16 g_d2hi[N_DRUG*256], g_d2lo[N_DRUG*256];
__device__ __nv_bfloat16 g_Xhi[NTOT*128],    g_Xlo[NTOT*128];
__device__ __nv_bfloat16 g_H1hi[NTOT*256],   g_H1lo[NTOT*256];
// bf16 hi/lo transposed weights
__device__ __nv_bfloat16 g_w1thi[128*176],  g_w1tlo[128*176];
__device__ __nv_bfloat16 g_w2thi[256*128],  g_w2tlo[256*128];
__device__ __nv_bfloat16 g_w3thi[128*256],  g_w3tlo[128*256];
__device__ __nv_bfloat16 g_gc1thi[256*128], g_gc1tlo[256*128];
__device__ __nv_bfloat16 g_gc23thi[256*256],g_gc23tlo[256*256];
__device__ __nv_bfloat16 g_W2dhi[N_PRO*256],g_W2dlo[N_PRO*256];
__device__ __nv_bfloat16 g_Gtthi[26L*128*256], g_Gttlo[26L*128*256];

__device__ __forceinline__ uint32_t smem_to_u32(const void* smem_ptr) {
    uint32_t addr;
    asm("{ .reg .u64 tmp; cvta.to.shared.u64 tmp, %1; cvt.u32.u64 %0, tmp; }"
        : "=r"(addr) : "l"(smem_ptr));
    return addr;
}

// ---------------- warp-level tensor-core primitives (sm_80+ baseline PTX) ----
#define LDSM_X4(r, addr) \
    asm volatile("ldmatrix.sync.aligned.m8n8.x4.shared.b16 {%0,%1,%2,%3}, [%4];" \
        : "=r"((r)[0]), "=r"((r)[1]), "=r"((r)[2]), "=r"((r)[3]) : "r"(addr))
#define LDSM_X2(r, addr) \
    asm volatile("ldmatrix.sync.aligned.m8n8.x2.shared.b16 {%0,%1}, [%2];" \
        : "=r"((r)[0]), "=r"((r)[1]) : "r"(addr))
#define MMA_BF16(c, a, b) \
    asm volatile("mma.sync.aligned.m16n8k16.row.col.f32.bf16.bf16.f32 " \
        "{%0,%1,%2,%3}, {%4,%5,%6,%7}, {%8,%9}, {%0,%1,%2,%3};" \
        : "+f"((c)[0]), "+f"((c)[1]), "+f"((c)[2]), "+f"((c)[3]) \
        : "r"((a)[0]), "r"((a)[1]), "r"((a)[2]), "r"((a)[3]), \
          "r"((b)[0]), "r"((b)[1]))

#define SY_PITCH_B 272
#define SY_TILE_BYTES (128 * SY_PITCH_B)          // 34816
#define GM_SMEM_TOTAL (4 * SY_TILE_BYTES)         // 139264 (gemm)
#define SY_SMEM_TOTAL (6 * SY_TILE_BYTES)         // 208896 (syrk, paired j)

__device__ __forceinline__ void bf16split(float v, __nv_bfloat16& h, __nv_bfloat16& l) {
    h = __float2bfloat16(v);
    l = __float2bfloat16(v - __bfloat162float(h));
}

// ---------------- CSR build ----------------
__global__ void count_kernel(const int* __restrict__ rows) {
    int e = blockIdx.x * 256 + threadIdx.x;
    if (e < NE) atomicAdd(&g_cnt[rows[e]], 1);
}
__global__ void scan_kernel() {
    __shared__ int sums[1024];
    int tid = threadIdx.x;
    const int CH = (NTOT + 1023) / 1024;   // 12
    int base = tid * CH;
    int s = 0;
    for (int i = 0; i < CH; i++) { int idx = base + i; if (idx < NTOT) s += g_cnt[idx]; }
    sums[tid] = s;
    __syncthreads();
    for (int off = 1; off < 1024; off <<= 1) {
        int v = 0;
        if (tid >= off) v = sums[tid - off];
        __syncthreads();
        sums[tid] += v;
        __syncthreads();
    }
    int prefix = (tid == 0) ? 0 : sums[tid - 1];
    for (int i = 0; i < CH; i++) {
        int idx = base + i;
        if (idx < NTOT) { g_rp[idx] = prefix; g_cur[idx] = prefix; prefix += g_cnt[idx]; }
    }
    if (tid == 1023) g_rp[NTOT] = NE;
}
__global__ void scatter_kernel(const int* __restrict__ rows, const int* __restrict__ cols,
                               const float* __restrict__ vals) {
    int e = blockIdx.x * 256 + threadIdx.x;
    if (e < NE) {
        int r = rows[e];
        int pos = atomicAdd(&g_cur[r], 1);
        g_ccol[pos] = cols[e];
        g_cval[pos] = vals[e];
    }
}

// ---------------- merged prep kernel (all weight splits/repacks) -------------
// block ranges:
#define PS0 7563                 // dxsplit       (11000*176/256)
#define PS1 (PS0 + 88)           // w1t
#define PS2 (PS1 + 128)          // w2t
#define PS3 (PS2 + 128)          // w3t
#define PS4 (PS3 + 128)          // gc1t
#define PS5 (PS4 + 256)          // gc23t
#define PS6 (PS5 + 1000)         // repack conv_w
#define PS7 (PS6 + 832)          // G per (t,o): 26*32 blocks
#define PS8 (PS7 + 1)            // pbias
__device__ __forceinline__ void prep_tsplit(int lidx, const float* __restrict__ W,
                                            int K, int N, int ldt,
                                            __nv_bfloat16* Thi, __nv_bfloat16* Tlo) {
    if (lidx < N * ldt) {
        int n = lidx / ldt, k = lidx - n * ldt;
        float v = (k < K) ? W[(long)k * N + n] : 0.f;
        bf16split(v, Thi[lidx], Tlo[lidx]);
    }
}
__global__ void prep_kernel(const float* __restrict__ dx,
                            const float* __restrict__ w1, const float* __restrict__ w2,
                            const float* __restrict__ w3, const float* __restrict__ gc1,
                            const float* __restrict__ gc2, const float* __restrict__ gc3,
                            const float* __restrict__ conv_w,
                            const float* __restrict__ emb, const float* __restrict__ fc_w,
                            const float* __restrict__ fc_b, const float* __restrict__ conv_b) {
    int b = blockIdx.x, tid = threadIdx.x;
    if (b < PS0) {
        int idx = b * 256 + tid;
        if (idx < N_DRUG * 176) {
            int row = idx / 176, col = idx - row * 176;
            float v = (col < 167) ? dx[(long)row * 167 + col] : 0.f;
            bf16split(v, g_dxhi[idx], g_dxlo[idx]);
        }
    } else if (b < PS1) {
        prep_tsplit((b - PS0) * 256 + tid, w1, 167, 128, 176, g_w1thi, g_w1tlo);
    } else if (b < PS2) {
        prep_tsplit((b - PS1) * 256 + tid, w2, 128, 256, 128, g_w2thi, g_w2tlo);
    } else if (b < PS3) {
        prep_tsplit((b - PS2) * 256 + tid, w3, 256, 128, 256, g_w3thi, g_w3tlo);
    } else if (b < PS4) {
        prep_tsplit((b - PS3) * 256 + tid, gc1, 128, 256, 128, g_gc1thi, g_gc1tlo);
    } else if (b < PS5) {
        int idx = (b - PS4) * 256 + tid;   // n*256 + k
        int n = idx >> 8, k = idx & 255;
        float v = (n < 128) ? gc2[k * 128 + n] : gc3[k * 128 + n - 128];
        bf16split(v, g_gc23thi[idx], g_gc23tlo[idx]);
    } else if (b < PS6) {
        int idx = (b - PS5) * 256 + tid;
        if (idx < N_PRO * 256) {
            int i = idx >> 8, ok = idx & 255;
            int o = ok >> 3, k = ok & 7;
            float v = conv_w[((long)o * N_PRO + i) * 8 + k];
            bf16split(v, g_W2dhi[idx], g_W2dlo[idx]);
        }
    } else if (b < PS7) {
        // G per (t,o): each fc_w row applied to 8 kk offsets (4 per thread-half).
        // Gtt[t][f][o*8+kk] = sum_h emb[t, h+kk] * fc_w[(o*121+h)*128 + f]
        __shared__ float e[128];
        int idx = b - PS6;
        int t = idx >> 5, o = idx & 31;
        int half = tid >> 7, f = tid & 127;
        if (tid < 128) e[tid] = emb[t * 128 + tid];
        __syncthreads();
        float acc[4] = {0.f, 0.f, 0.f, 0.f};
        const float* wrow = fc_w + (long)o * 121 * 128 + f;
        int kbase = half * 4;
        for (int h = 0; h < 121; h++) {
            float w = wrow[h * 128];
#pragma unroll
            for (int kk = 0; kk < 4; kk++)
                acc[kk] += e[h + kbase + kk] * w;
        }
        long dbase = ((long)t * 128 + f) * 256 + o * 8 + kbase;
#pragma unroll
        for (int kk = 0; kk < 4; kk++)
            bf16split(acc[kk], g_Gtthi[dbase + kk], g_Gttlo[dbase + kk]);
    } else {
        int f = tid;
        if (f < 128) {
            float acc = fc_b[f];
            for (int o = 0; o < 32; o++) {
                float cb = conv_b[o];
                for (int h = 0; h < 121; h++) acc += cb * fc_w[(o * 121 + h) * 128 + f];
            }
            g_pbias[f] = acc;
        }
    }
}

__global__ void protein_gather_kernel(const int* __restrict__ pro_x) {
    int p = blockIdx.x, f = threadIdx.x;   // 1000 blocks x 128
    __shared__ int tok[128];
    float acc = g_pbias[f];
    for (int c = 0; c < 1000; c += 128) {
        int n = min(128, 1000 - c);
        if (f < n) tok[f] = pro_x[p * 1000 + c + f];
        __syncthreads();
#pragma unroll 8
        for (int ii = 0; ii < n; ii++) {
            int t = tok[ii];
            acc += __half2float(g_M16[((long)t * N_PRO + c + ii) * 128 + f]);
        }
        __syncthreads();
    }
    long dst = (long)(N_DRUG + p) * 128 + f;
    bf16split(acc, g_Xhi[dst], g_Xlo[dst]);
}

// ---------------- SpMM (CSR gather), F=256 ----------------------------------
__global__ void spmm256_kernel(const float* __restrict__ Xin,
                               float* __restrict__ out1, float* __restrict__ out2,
                               __nv_bfloat16* __restrict__ bh, __nv_bfloat16* __restrict__ bl,
                               int relu, int split128) {
    int r = blockIdx.x;
    int f = threadIdx.x;   // 256
    int e0 = g_rp[r], e1 = g_rp[r + 1];
    float acc = 0.f;
    for (int e = e0; e < e1; e++) {
        int c = g_ccol[e];
        float v = g_cval[e];
        acc += v * Xin[(long)c * 256 + f];
    }
    if (relu) acc = fmaxf(acc, 0.f);
    if (split128) {
        if (f < 128) {
            out1[(long)r * 128 + f] = acc;
            bf16split(acc, bh[(long)r * 128 + f], bl[(long)r * 128 + f]);
        } else {
            out2[(long)r * 128 + f - 128] = acc;
        }
    } else {
        bf16split(acc, bh[(long)r * 256 + f], bl[(long)r * 256 + f]);
    }
}

// ---------------- tensor-core GEMM: C[M,N] = A[M,K] @ Bt[N,K]^T --------------
__global__ __launch_bounds__(256, 1) void gemm_mma_kernel(
    const __nv_bfloat16* __restrict__ Ahi, const __nv_bfloat16* __restrict__ Alo, int lda,
    const __nv_bfloat16* __restrict__ Bhi, const __nv_bfloat16* __restrict__ Blo, int ldb,
    const float* __restrict__ bias,
    float* __restrict__ Cf, __half* __restrict__ C16,
    __nv_bfloat16* __restrict__ Chi, __nv_bfloat16* __restrict__ Clo,
    int ldc, int M, int N, int K, int relu, long sB, long sC)
{
    Bhi += (long)blockIdx.z * sB;
    Blo += (long)blockIdx.z * sB;
    long coff = (long)blockIdx.z * sC;
    extern __shared__ char smem[];
    uint32_t sb = smem_to_u32(smem);

    int tid = threadIdx.x, lane = tid & 31, wid = tid >> 5;
    int m0 = blockIdx.y * 128, n0 = blockIdx.x * 128;

    int mw = (wid & 1) << 6;
    int nw = (wid >> 1) << 5;
    float acc[4][4][4];
#pragma unroll
    for (int a = 0; a < 4; a++)
#pragma unroll
        for (int b = 0; b < 4; b++)
#pragma unroll
            for (int c = 0; c < 4; c++) acc[a][b][c] = 0.f;

    int arow = mw + (lane & 15);
    uint32_t acol = ((uint32_t)(lane >> 4)) * 16u;
    int brow = nw + (lane & 7);
    uint32_t bcol = ((uint32_t)((lane >> 3) & 1)) * 16u;

    int r = tid >> 1, half = tid & 1;

    for (int k0 = 0; k0 < K; k0 += 128) {
        {
            const __nv_bfloat16* srcs[4] = {Ahi, Alo, Bhi, Blo};
            int lds[4]   = {lda, lda, ldb, ldb};
            int base[4]  = {m0, m0, n0, n0};
            int limit[4] = {M, M, N, N};
#pragma unroll
            for (int tI = 0; tI < 4; tI++) {
                long gr = (long)base[tI] + r;
                bool rv = gr < limit[tI];
                const __nv_bfloat16* sp = srcs[tI] + gr * (long)lds[tI] + k0 + half * 64;
                uint4* d = (uint4*)(smem + tI * SY_TILE_BYTES + r * SY_PITCH_B + half * 128);
#pragma unroll
                for (int c = 0; c < 8; c++) {
                    int col0 = half * 64 + c * 8;
                    uint4 v = make_uint4(0, 0, 0, 0);
                    if (rv && (k0 + col0 + 8) <= K) v = *(const uint4*)(sp + c * 8);
                    d[c] = v;
                }
            }
        }
        __syncthreads();

        int ksteps = (K - k0) >= 128 ? 8 : ((K - k0 + 15) >> 4);
        uint32_t offA_hi = 0, offA_lo = SY_TILE_BYTES;
        uint32_t offB_hi = 2u * SY_TILE_BYTES, offB_lo = 3u * SY_TILE_BYTES;
        for (int ks = 0; ks < ksteps; ks++) {
            uint32_t kb = (uint32_t)ks * 32u;
            uint32_t bh[4][2], bl[4][2];
#pragma unroll
            for (int nf = 0; nf < 4; nf++) {
                uint32_t ro = (uint32_t)(brow + nf * 8) * SY_PITCH_B + kb + bcol;
                LDSM_X2(bh[nf], sb + offB_hi + ro);
                LDSM_X2(bl[nf], sb + offB_lo + ro);
            }
#pragma unroll
            for (int mf = 0; mf < 4; mf++) {
                uint32_t ro = (uint32_t)(arow + mf * 16) * SY_PITCH_B + kb + acol;
                uint32_t ah[4], al[4];
                LDSM_X4(ah, sb + offA_hi + ro);
                LDSM_X4(al, sb + offA_lo + ro);
#pragma unroll
                for (int nf = 0; nf < 4; nf++) {
                    MMA_BF16(acc[mf][nf], ah, bh[nf]);
                    MMA_BF16(acc[mf][nf], ah, bl[nf]);
                    MMA_BF16(acc[mf][nf], al, bh[nf]);
                }
            }
        }
        __syncthreads();
    }

    // epilogue
    int mrow = lane >> 2, ncol = (lane & 3) * 2;
#pragma unroll
    for (int mf = 0; mf < 4; mf++) {
#pragma unroll
        for (int nf = 0; nf < 4; nf++) {
            long gm = m0 + mw + mf * 16 + mrow;
            int gn = n0 + nw + nf * 8 + ncol;
            float v0 = acc[mf][nf][0], v1 = acc[mf][nf][1];
            float v2 = acc[mf][nf][2], v3 = acc[mf][nf][3];
            if (bias) {
                float b0 = bias[gn], b1 = bias[gn + 1];
                v0 += b0; v1 += b1; v2 += b0; v3 += b1;
            }
            if (relu) {
                v0 = fmaxf(v0, 0.f); v1 = fmaxf(v1, 0.f);
                v2 = fmaxf(v2, 0.f); v3 = fmaxf(v3, 0.f);
            }
            if (gm < M) {
                long o = coff + gm * (long)ldc + gn;
                if (Cf) *(float2*)&Cf[o] = make_float2(v0, v1);
                if (C16) *(__half2*)&C16[o] = __floats2half2_rn(v0, v1);
                if (Chi) {
                    __nv_bfloat162 h, l;
                    bf16split(v0, h.x, l.x); bf16split(v1, h.y, l.y);
                    *(__nv_bfloat162*)&Chi[o] = h;
                    *(__nv_bfloat162*)&Clo[o] = l;
                }
            }
            if (gm + 8 < M) {
                long o = coff + (gm + 8) * (long)ldc + gn;
                if (Cf) *(float2*)&Cf[o] = make_float2(v2, v3);
                if (C16) *(__half2*)&C16[o] = __floats2half2_rn(v2, v3);
                if (Chi) {
                    __nv_bfloat162 h, l;
                    bf16split(v2, h.x, l.x); bf16split(v3, h.y, l.y);
                    *(__nv_bfloat162*)&Chi[o] = h;
                    *(__nv_bfloat162*)&Clo[o] = l;
                }
            }
        }
    }
}

// ---------------- SYRK via mma.sync bf16 hi/lo: C = Z Z^T --------------------
// Paired-j: one CTA handles tiles (i,j0) and (i,j0+1). Smem: 6 tiles.
__device__ __forceinline__ void ld_tile(char* smem, int off,
                                        const __nv_bfloat16* __restrict__ src,
                                        long row0, int r, int half) {
    long gr = row0 + r;
    uint4 v[8];
    if (gr < NTOT) {
        const uint4* s = reinterpret_cast<const uint4*>(src + gr * 128 + half * 64);
#pragma unroll
        for (int c = 0; c < 8; c++) v[c] = s[c];
    } else {
#pragma unroll
        for (int c = 0; c < 8; c++) v[c] = make_uint4(0, 0, 0, 0);
    }
    uint4* d = reinterpret_cast<uint4*>(smem + off + r * SY_PITCH_B + half * 128);
#pragma unroll
    for (int c = 0; c < 8; c++) d[c] = v[c];
}

__device__ __forceinline__ void syrk_tile(uint32_t sb, uint32_t offBh, uint32_t offBl,
                                          long i0, long j0, bool mirror,
                                          float* __restrict__ C, int lane, int wid) {
    int mw = (wid & 1) << 6;
    int nw = (wid >> 1) << 5;
    float acc[4][4][4];
#pragma unroll
    for (int a = 0; a < 4; a++)
#pragma unroll
        for (int b = 0; b < 4; b++)
#pragma unroll
            for (int c = 0; c < 4; c++) acc[a][b][c] = 0.f;

    int arow = mw + (lane & 15);
    uint32_t acol = ((uint32_t)(lane >> 4)) * 16u;
    int brow = nw + (lane & 7);
    uint32_t bcol = ((uint32_t)((lane >> 3) & 1)) * 16u;

#pragma unroll
    for (int ks = 0; ks < 8; ks++) {
        uint32_t kb = (uint32_t)ks * 32u;
        uint32_t bh[4][2], bl[4][2];
#pragma unroll
        for (int nf = 0; nf < 4; nf++) {
            uint32_t ro = (uint32_t)(brow + nf * 8) * SY_PITCH_B + kb + bcol;
            LDSM_X2(bh[nf], sb + offBh + ro);
            LDSM_X2(bl[nf], sb + offBl + ro);
        }
#pragma unroll
        for (int mf = 0; mf < 4; mf++) {
            uint32_t ro = (uint32_t)(arow + mf * 16) * SY_PITCH_B + kb + acol;
            uint32_t ah[4], al[4];
            LDSM_X4(ah, sb + 0 + ro);
            LDSM_X4(al, sb + SY_TILE_BYTES + ro);
#pragma unroll
            for (int nf = 0; nf < 4; nf++) {
                MMA_BF16(acc[mf][nf], ah, bh[nf]);
                MMA_BF16(acc[mf][nf], ah, bl[nf]);
                MMA_BF16(acc[mf][nf], al, bh[nf]);
            }
        }
    }

    int mrow = lane >> 2, ncol = (lane & 3) * 2;
#pragma unroll
    for (int mf = 0; mf < 4; mf++) {
#pragma unroll
        for (int nf = 0; nf < 4; nf++) {
            long gm = i0 + mw + mf * 16 + mrow;
            long gn = j0 + nw + nf * 8 + ncol;
            float v0 = acc[mf][nf][0], v1 = acc[mf][nf][1];
            float v2 = acc[mf][nf][2], v3 = acc[mf][nf][3];
            if (gn < NTOT) {
                if (gm < NTOT)
                    *(float2*)&C[gm * (long)NTOT + gn] = make_float2(v0, v1);
                if (gm + 8 < NTOT)
                    *(float2*)&C[(gm + 8) * (long)NTOT + gn] = make_float2(v2, v3);
            }
            if (mirror) {
                if (gn < NTOT) {
                    if (gm < NTOT)      C[gn * (long)NTOT + gm] = v0;
                    if (gm + 8 < NTOT)  C[gn * (long)NTOT + gm + 8] = v2;
                }
                if (gn + 1 < NTOT) {
                    if (gm < NTOT)      C[(gn + 1) * (long)NTOT + gm] = v1;
                    if (gm + 8 < NTOT)  C[(gn + 1) * (long)NTOT + gm + 8] = v3;
                }
            }
        }
    }
}

__global__ __launch_bounds__(256, 1) void syrk_mma_kernel(float* __restrict__ C) {
    extern __shared__ char smem[];
    int rem = blockIdx.x;
    int i = 0;
    while (true) {
        int np = (95 - i) >> 1;
        if (rem < np) break;
        rem -= np;
        i++;
    }
    int j0 = i + 2 * rem;
    int j1 = j0 + 1;
    bool has2 = (j1 <= 93);
    long i0 = (long)i * 128, jj0 = (long)j0 * 128, jj1 = (long)j1 * 128;

    int tid = threadIdx.x, lane = tid & 31, wid = tid >> 5;

    {
        int r = tid >> 1, half = tid & 1;
        ld_tile(smem, 0,                 g_Zhi, i0, r, half);
        ld_tile(smem, SY_TILE_BYTES,     g_Zlo, i0, r, half);
        ld_tile(smem, 2 * SY_TILE_BYTES, g_Zhi, jj0, r, half);
        ld_tile(smem, 3 * SY_TILE_BYTES, g_Zlo, jj0, r, half);
        if (has2) {
            ld_tile(smem, 4 * SY_TILE_BYTES, g_Zhi, jj1, r, half);
            ld_tile(smem, 5 * SY_TILE_BYTES, g_Zlo, jj1, r, half);
        }
    }
    __syncthreads();

    uint32_t sb = smem_to_u32(smem);
    syrk_tile(sb, 2u * SY_TILE_BYTES, 3u * SY_TILE_BYTES, i0, jj0, j0 != i, C, lane, wid);
    if (has2)
        syrk_tile(sb, 4u * SY_TILE_BYTES, 5u * SY_TILE_BYTES, i0, jj1, true, C, lane, wid);
}

// ---------------- host ----------------
extern "C" void kernel_launch(void* const* d_in, const int* in_sizes, int n_in,
                              void* d_out, int out_size) {
    const float* drug_x = (const float*)d_in[0];
    const int*   pro_x  = (const int*)d_in[1];
    const int*   arows  = (const int*)d_in[2];
    const int*   acols  = (const int*)d_in[3];
    const float* avals  = (const float*)d_in[4];
    const float* w1     = (const float*)d_in[5];
    const float* b1     = (const float*)d_in[6];
    const float* w2     = (const float*)d_in[7];
    const float* b2     = (const float*)d_in[8];
    const float* w3     = (const float*)d_in[9];
    const float* b3     = (const float*)d_in[10];
    const float* emb_xt = (const float*)d_in[11];
    const float* conv_w = (const float*)d_in[12];
    const float* conv_b = (const float*)d_in[13];
    const float* fc_w   = (const float*)d_in[14];
    const float* fc_b   = (const float*)d_in[15];
    const float* gc1_w  = (const float*)d_in[16];
    const float* gc2_w  = (const float*)d_in[17];
    const float* gc3_w  = (const float*)d_in[18];
    float* out = (float*)d_out;

    float *pXW1, *pHW;
    __half* pM16;
    int *pcnt;
    cudaGetSymbolAddress((void**)&pM16, g_M16);
    cudaGetSymbolAddress((void**)&pXW1, g_XW1);
    cudaGetSymbolAddress((void**)&pHW,  g_HW);
    cudaGetSymbolAddress((void**)&pcnt, g_cnt);
    __nv_bfloat16 *pdxh,*pdxl,*pd1h,*pd1l,*pd2h,*pd2l,*pXh,*pXl,*pH1h,*pH1l;
    __nv_bfloat16 *pw1h,*pw1l,*pw2h,*pw2l,*pw3h,*pw3l,*pg1h,*pg1l,*pg23h,*pg23l;
    __nv_bfloat16 *pW2h,*pW2l,*pGth,*pGtl,*pZh,*pZl;
    cudaGetSymbolAddress((void**)&pdxh, g_dxhi);  cudaGetSymbolAddress((void**)&pdxl, g_dxlo);
    cudaGetSymbolAddress((void**)&pd1h, g_d1hi);  cudaGetSymbolAddress((void**)&pd1l, g_d1lo);
    cudaGetSymbolAddress((void**)&pd2h, g_d2hi);  cudaGetSymbolAddress((void**)&pd2l, g_d2lo);
    cudaGetSymbolAddress((void**)&pXh,  g_Xhi);   cudaGetSymbolAddress((void**)&pXl,  g_Xlo);
    cudaGetSymbolAddress((void**)&pH1h, g_H1hi);  cudaGetSymbolAddress((void**)&pH1l, g_H1lo);
    cudaGetSymbolAddress((void**)&pw1h, g_w1thi); cudaGetSymbolAddress((void**)&pw1l, g_w1tlo);
    cudaGetSymbolAddress((void**)&pw2h, g_w2thi); cudaGetSymbolAddress((void**)&pw2l, g_w2tlo);
    cudaGetSymbolAddress((void**)&pw3h, g_w3thi); cudaGetSymbolAddress((void**)&pw3l, g_w3tlo);
    cudaGetSymbolAddress((void**)&pg1h, g_gc1thi);cudaGetSymbolAddress((void**)&pg1l, g_gc1tlo);
    cudaGetSymbolAddress((void**)&pg23h,g_gc23thi);cudaGetSymbolAddress((void**)&pg23l,g_gc23tlo);
    cudaGetSymbolAddress((void**)&pW2h, g_W2dhi); cudaGetSymbolAddress((void**)&pW2l, g_W2dlo);
    cudaGetSymbolAddress((void**)&pGth, g_Gtthi); cudaGetSymbolAddress((void**)&pGtl, g_Gttlo);
    cudaGetSymbolAddress((void**)&pZh,  g_Zhi);   cudaGetSymbolAddress((void**)&pZl,  g_Zlo);

    static int smem_set = 0;
    if (!smem_set) {
        cudaFuncSetAttribute(syrk_mma_kernel, cudaFuncAttributeMaxDynamicSharedMemorySize,
                             SY_SMEM_TOTAL);
        cudaFuncSetAttribute(gemm_mma_kernel, cudaFuncAttributeMaxDynamicSharedMemorySize,
                             GM_SMEM_TOTAL);
        smem_set = 1;
    }

    // CSR build
    cudaMemsetAsync(pcnt, 0, NTOT * sizeof(int));
    count_kernel<<<750, 256>>>(arows);
    scan_kernel<<<1, 1024>>>();
    scatter_kernel<<<750, 256>>>(arows, acols, avals);

    // merged prep (all splits/repacks/G/pbias)
    prep_kernel<<<PS8, 256>>>(drug_x, w1, w2, w3, gc1_w, gc2_w, gc3_w,
                              conv_w, emb_xt, fc_w, fc_b, conv_b);

    // drug MLP (tensor cores)
    gemm_mma_kernel<<<dim3(1, 86, 1), 256, GM_SMEM_TOTAL>>>(
        pdxh, pdxl, 176, pw1h, pw1l, 176, b1,
        nullptr, nullptr, pd1h, pd1l, 128, N_DRUG, 128, 176, 1, 0, 0);
    gemm_mma_kernel<<<dim3(2, 86, 1), 256, GM_SMEM_TOTAL>>>(
        pd1h, pd1l, 128, pw2h, pw2l, 128, b2,
        nullptr, nullptr, pd2h, pd2l, 256, N_DRUG, 256, 128, 1, 0, 0);
    gemm_mma_kernel<<<dim3(1, 86, 1), 256, GM_SMEM_TOTAL>>>(
        pd2h, pd2l, 256, pw3h, pw3l, 256, b3,
        nullptr, nullptr, pXh, pXl, 128, N_DRUG, 128, 256, 1, 0, 0);

    // protein: M[t] = W2d @ Gt[t]  (batched, tensor cores, fp16 output)
    gemm_mma_kernel<<<dim3(1, 8, 26), 256, GM_SMEM_TOTAL>>>(
        pW2h, pW2l, 256, pGth, pGtl, 256, nullptr,
        nullptr, pM16, nullptr, nullptr, 128, N_PRO, 128, 256, 0,
        128L * 256, (long)N_PRO * 128);
    protein_gather_kernel<<<1000, 128>>>(pro_x);

    // GCN encoder
    gemm_mma_kernel<<<dim3(2, 94, 1), 256, GM_SMEM_TOTAL>>>(
        pXh, pXl, 128, pg1h, pg1l, 128, nullptr,
        pXW1, nullptr, nullptr, nullptr, 256, NTOT, 256, 128, 0, 0, 0);
    spmm256_kernel<<<NTOT, 256>>>(pXW1, nullptr, nullptr, pH1h, pH1l, 1, 0);
    gemm_mma_kernel<<<dim3(2, 94, 1), 256, GM_SMEM_TOTAL>>>(
        pH1h, pH1l, 256, pg23h, pg23l, 256, nullptr,
        pHW, nullptr, nullptr, nullptr, 256, NTOT, 256, 256, 0, 0, 0);
    spmm256_kernel<<<NTOT, 256>>>(pHW, out + OFF_MU, out + OFF_LV, pZh, pZl, 0, 1);

    // decoder: adj_rec = Z Z^T (paired-j tiles)
    syrk_mma_kernel<<<2256, 256, SY_SMEM_TOTAL>>>(out);
}